// round 6
// baseline (speedup 1.0000x reference)
#include <cuda_runtime.h>
#include <cuda_bf16.h>
#include <cstdint>
#include <cstddef>

typedef __nv_bfloat16 bf16;

#define BATCH 256
#define TT    128
#define DD    1024
#define HH    1024
#define GG    3072
#define BT    (BATCH*TT)   // 32768
#define SCAN_BLOCKS 128

// ---------------- device scratch (static; no runtime allocation) ----------------
__device__ float g_gi[(size_t)BT * GG];                 // 402 MB
__device__ bf16  g_xhi[(size_t)BT * DD];
__device__ bf16  g_xlo[(size_t)BT * DD];
__device__ bf16  g_wih_hi[(size_t)GG * DD];
__device__ bf16  g_wih_lo[(size_t)GG * DD];
__device__ bf16  g_whh_hi[(size_t)GG * HH];
__device__ bf16  g_whh_lo[(size_t)GG * HH];
__device__ float g_h[2][BATCH * HH];
__device__ bf16  g_hhi[2][BATCH * HH];
__device__ bf16  g_hlo[2][BATCH * HH];
__device__ float g_mask[BT];
__device__ unsigned g_bar_arrive;   // zero-init; self-restoring
__device__ unsigned g_bar_gen;      // monotonically increasing across replays (equality-compared)

// ---------------- helpers ----------------
__device__ __forceinline__ void cp16(uint32_t dst, const void* src) {
    asm volatile("cp.async.cg.shared.global [%0], [%1], 16;\n" :: "r"(dst), "l"(src));
}
__device__ __forceinline__ void cp_commit() { asm volatile("cp.async.commit_group;\n"); }
template<int N> __device__ __forceinline__ void cp_wait() {
    asm volatile("cp.async.wait_group %0;\n" :: "n"(N));
}
__device__ __forceinline__ void ldm4(uint32_t* r, uint32_t a) {
    asm volatile("ldmatrix.sync.aligned.m8n8.x4.shared.b16 {%0,%1,%2,%3},[%4];\n"
                 : "=r"(r[0]), "=r"(r[1]), "=r"(r[2]), "=r"(r[3]) : "r"(a));
}
__device__ __forceinline__ void ldm2(uint32_t* r, uint32_t a) {
    asm volatile("ldmatrix.sync.aligned.m8n8.x2.shared.b16 {%0,%1},[%2];\n"
                 : "=r"(r[0]), "=r"(r[1]) : "r"(a));
}
__device__ __forceinline__ void mma16816(float* c, const uint32_t* a, const uint32_t* b) {
    asm volatile("mma.sync.aligned.m16n8k16.row.col.f32.bf16.bf16.f32 "
                 "{%0,%1,%2,%3},{%4,%5,%6,%7},{%8,%9},{%0,%1,%2,%3};\n"
                 : "+f"(c[0]), "+f"(c[1]), "+f"(c[2]), "+f"(c[3])
                 : "r"(a[0]), "r"(a[1]), "r"(a[2]), "r"(a[3]), "r"(b[0]), "r"(b[1]));
}
// smem rows are 64B (32 halves); chunk = 16B unit; XOR swizzle on (row&3)
__device__ __forceinline__ uint32_t sw(uint32_t base, int r, int c) {
    return base + (r << 6) + ((c ^ (r & 3)) << 4);
}
__device__ __forceinline__ float sigmoidf_(float x) { return 1.f / (1.f + expf(-x)); }

// GPU-wide barrier (all SCAN_BLOCKS blocks resident; one wave guaranteed).
__device__ __forceinline__ void grid_sync_() {
    __threadfence();
    __syncthreads();
    if (threadIdx.x == 0) {
        unsigned gen;
        asm volatile("ld.acquire.gpu.u32 %0, [%1];" : "=r"(gen) : "l"(&g_bar_gen));
        unsigned ticket = atomicAdd(&g_bar_arrive, 1u);
        if (ticket == SCAN_BLOCKS - 1u) {
            g_bar_arrive = 0u;
            __threadfence();
            atomicAdd(&g_bar_gen, 1u);
        } else {
            unsigned cur;
            do {
                asm volatile("ld.acquire.gpu.u32 %0, [%1];" : "=r"(cur) : "l"(&g_bar_gen));
            } while (cur == gen);
        }
    }
    __syncthreads();
}

// ---------------- prep kernels ----------------
__global__ void mask_kernel(const void* __restrict__ isin) {
    __shared__ int is32;
    if (threadIdx.x == 0) {
        const unsigned char* p = (const unsigned char*)isin;
        int ok = 1;
        for (int i = 0; i < 1024; i++) {
            if (p[4 * i + 1] | p[4 * i + 2] | p[4 * i + 3]) { ok = 0; break; }
        }
        is32 = ok;
    }
    __syncthreads();
    int start = blockIdx.x * blockDim.x + threadIdx.x;
    int stride = gridDim.x * blockDim.x;
    if (is32) {
        const int* q = (const int*)isin;
        for (int i = start; i < BT; i += stride) g_mask[i] = q[i] ? 0.f : 1.f;
    } else {
        const unsigned char* q = (const unsigned char*)isin;
        for (int i = start; i < BT; i += stride) g_mask[i] = q[i] ? 0.f : 1.f;
    }
}

__global__ void split_x_kernel(const float* __restrict__ x) {
    size_t n = (size_t)BT * DD;
    for (size_t i = blockIdx.x * (size_t)blockDim.x + threadIdx.x; i < n;
         i += (size_t)gridDim.x * blockDim.x) {
        float f = x[i];
        bf16 h = __float2bfloat16(f);
        g_xhi[i] = h;
        g_xlo[i] = __float2bfloat16(f - __bfloat162float(h));
    }
}
__global__ void split_wih_kernel(const float* __restrict__ w) {
    size_t n = (size_t)GG * DD;
    for (size_t i = blockIdx.x * (size_t)blockDim.x + threadIdx.x; i < n;
         i += (size_t)gridDim.x * blockDim.x) {
        float f = w[i];
        bf16 h = __float2bfloat16(f);
        g_wih_hi[i] = h;
        g_wih_lo[i] = __float2bfloat16(f - __bfloat162float(h));
    }
}
__global__ void split_whh_kernel(const float* __restrict__ w) {
    size_t n = (size_t)GG * HH;
    for (size_t i = blockIdx.x * (size_t)blockDim.x + threadIdx.x; i < n;
         i += (size_t)gridDim.x * blockDim.x) {
        float f = w[i];
        bf16 h = __float2bfloat16(f);
        g_whh_hi[i] = h;
        g_whh_lo[i] = __float2bfloat16(f - __bfloat162float(h));
    }
}
__global__ void init_h_kernel(const float* __restrict__ hx) {
    int n = BATCH * HH;
    for (int i = blockIdx.x * blockDim.x + threadIdx.x; i < n; i += gridDim.x * blockDim.x) {
        float f = hx[i];
        g_h[0][i] = f;
        bf16 h = __float2bfloat16(f);
        g_hhi[0][i] = h;
        g_hlo[0][i] = __float2bfloat16(f - __bfloat162float(h));
    }
}

// ---------------- gi = x @ W_ih^T + b_ih (split-bf16, 3-MMA) ----------------
// grid (GG/64, BT/128), block 256
__global__ __launch_bounds__(256) void gi_gemm(const float* __restrict__ b_ih) {
    __shared__ __align__(16) char smem[49152];
    uint32_t sb = (uint32_t)__cvta_generic_to_shared(smem);
    int tid = threadIdx.x, lane = tid & 31, w = tid >> 5;
    int wm = w & 3, wn = w >> 2;
    int m0 = blockIdx.y * 128, n0 = blockIdx.x * 64;

    float acc[2][4][4];
#pragma unroll
    for (int i = 0; i < 2; i++)
#pragma unroll
        for (int j = 0; j < 4; j++)
#pragma unroll
            for (int e = 0; e < 4; e++) acc[i][j][e] = 0.f;

    auto load_stage = [&](int kt, int s) {
        uint32_t o = sb + s * 24576;
        int k0 = kt * 32;
#pragma unroll
        for (int v = tid; v < 512; v += 256) {
            int r = v >> 2, c = v & 3;
            const bf16* sh = g_xhi + (size_t)(m0 + r) * DD + k0 + c * 8;
            const bf16* sl = g_xlo + (size_t)(m0 + r) * DD + k0 + c * 8;
            cp16(sw(o, r, c), sh);
            cp16(sw(o + 8192, r, c), sl);
        }
        {
            int v = tid;
            int r = v >> 2, c = v & 3;
            cp16(sw(o + 16384, r, c), g_wih_hi + (size_t)(n0 + r) * DD + k0 + c * 8);
            cp16(sw(o + 20480, r, c), g_wih_lo + (size_t)(n0 + r) * DD + k0 + c * 8);
        }
        cp_commit();
    };

    load_stage(0, 0);
    const int KT = DD / 32;
    for (int kt = 0; kt < KT; kt++) {
        if (kt + 1 < KT) load_stage(kt + 1, (kt + 1) & 1);
        if (kt + 1 < KT) cp_wait<1>(); else cp_wait<0>();
        __syncthreads();
        uint32_t o = sb + (kt & 1) * 24576;
#pragma unroll
        for (int kk = 0; kk < 2; kk++) {
            uint32_t ah[2][4], al[2][4], bh[4][2], bl[4][2];
#pragma unroll
            for (int i = 0; i < 2; i++) {
                int r = wm * 32 + i * 16 + (lane & 15);
                int c = kk * 2 + (lane >> 4);
                ldm4(ah[i], sw(o, r, c));
                ldm4(al[i], sw(o + 8192, r, c));
            }
#pragma unroll
            for (int sg = 0; sg < 2; sg++) {
                int r = wn * 32 + sg * 16 + ((lane >> 4) & 1) * 8 + (lane & 7);
                int c = kk * 2 + ((lane >> 3) & 1);
                uint32_t t4[4];
                ldm4(t4, sw(o + 16384, r, c));
                bh[sg * 2][0] = t4[0]; bh[sg * 2][1] = t4[1];
                bh[sg * 2 + 1][0] = t4[2]; bh[sg * 2 + 1][1] = t4[3];
                ldm4(t4, sw(o + 20480, r, c));
                bl[sg * 2][0] = t4[0]; bl[sg * 2][1] = t4[1];
                bl[sg * 2 + 1][0] = t4[2]; bl[sg * 2 + 1][1] = t4[3];
            }
#pragma unroll
            for (int i = 0; i < 2; i++)
#pragma unroll
                for (int j = 0; j < 4; j++) {
                    mma16816(acc[i][j], ah[i], bh[j]);
                    mma16816(acc[i][j], ah[i], bl[j]);
                    mma16816(acc[i][j], al[i], bh[j]);
                }
        }
        __syncthreads();
    }

#pragma unroll
    for (int i = 0; i < 2; i++) {
        int row = m0 + wm * 32 + i * 16 + (lane >> 2);
#pragma unroll
        for (int j = 0; j < 4; j++) {
            int col = n0 + wn * 32 + j * 8 + (lane & 3) * 2;
            float b0 = b_ih[col], b1 = b_ih[col + 1];
            g_gi[(size_t)row * GG + col]           = acc[i][j][0] + b0;
            g_gi[(size_t)row * GG + col + 1]       = acc[i][j][1] + b1;
            g_gi[(size_t)(row + 8) * GG + col]     = acc[i][j][2] + b0;
            g_gi[(size_t)(row + 8) * GG + col + 1] = acc[i][j][3] + b1;
        }
    }
}

// ---------------- persistent GRU scan: 128 steps in one kernel ----------------
// grid (HH/32, BATCH/64) = (32,4) = 128 blocks, block 256
__global__ __launch_bounds__(256) void gru_scan(const float* __restrict__ b_hh,
                                                float* __restrict__ hseq_out) {
    __shared__ __align__(16) char smem[40960];
    uint32_t sb = (uint32_t)__cvta_generic_to_shared(smem);
    int tid = threadIdx.x, lane = tid & 31, w = tid >> 5;
    int wm = w & 1, wn = w >> 1;
    int m0 = blockIdx.y * 64, n0 = blockIdx.x * 32;

    // hoist per-thread gate biases (epilogue columns are t-invariant)
    int cbase = n0 + wn * 8 + (lane & 3) * 2;
    float bias_r[2], bias_z[2], bias_n[2];
#pragma unroll
    for (int e = 0; e < 2; e++) {
        bias_r[e] = b_hh[cbase + e];
        bias_z[e] = b_hh[1024 + cbase + e];
        bias_n[e] = b_hh[2048 + cbase + e];
    }

    for (int t = 0; t < TT; t++) {
        int cur = t & 1, nxt = cur ^ 1;

        float acc[3][2][4];
#pragma unroll
        for (int g = 0; g < 3; g++)
#pragma unroll
            for (int i = 0; i < 2; i++)
#pragma unroll
                for (int e = 0; e < 4; e++) acc[g][i][e] = 0.f;

        auto load_stage = [&](int kt, int s) {
            uint32_t o = sb + s * 20480;
            int k0 = kt * 32;
            {
                int v = tid;  // 64 rows x 4 chunks = 256 exactly
                int r = v >> 2, c = v & 3;
                cp16(sw(o, r, c), g_hhi[cur] + (size_t)(m0 + r) * HH + k0 + c * 8);
                cp16(sw(o + 4096, r, c), g_hlo[cur] + (size_t)(m0 + r) * HH + k0 + c * 8);
            }
#pragma unroll
            for (int v = tid; v < 384; v += 256) {  // 96 rows x 4 chunks
                int r = v >> 2, c = v & 3;
                size_t grow = (size_t)((r >> 5) * HH + n0 + (r & 31));
                cp16(sw(o + 8192, r, c), g_whh_hi + grow * HH + k0 + c * 8);
                cp16(sw(o + 14336, r, c), g_whh_lo + grow * HH + k0 + c * 8);
            }
            cp_commit();
        };

        load_stage(0, 0);
        const int KT = HH / 32;
        for (int kt = 0; kt < KT; kt++) {
            if (kt + 1 < KT) load_stage(kt + 1, (kt + 1) & 1);
            if (kt + 1 < KT) cp_wait<1>(); else cp_wait<0>();
            __syncthreads();
            uint32_t o = sb + (kt & 1) * 20480;
#pragma unroll
            for (int kk = 0; kk < 2; kk++) {
                uint32_t ah[2][4], al[2][4], bh[3][2], bl[3][2];
#pragma unroll
                for (int i = 0; i < 2; i++) {
                    int r = wm * 32 + i * 16 + (lane & 15);
                    int c = kk * 2 + (lane >> 4);
                    ldm4(ah[i], sw(o, r, c));
                    ldm4(al[i], sw(o + 4096, r, c));
                }
#pragma unroll
                for (int g = 0; g < 3; g++) {
                    int l = lane & 15;
                    int r = g * 32 + wn * 8 + (l & 7);
                    int c = kk * 2 + (l >> 3);
                    ldm2(bh[g], sw(o + 8192, r, c));
                    ldm2(bl[g], sw(o + 14336, r, c));
                }
#pragma unroll
                for (int g = 0; g < 3; g++)
#pragma unroll
                    for (int i = 0; i < 2; i++) {
                        mma16816(acc[g][i], ah[i], bh[g]);
                        mma16816(acc[g][i], ah[i], bl[g]);
                        mma16816(acc[g][i], al[i], bh[g]);
                    }
            }
            __syncthreads();
        }

        // fused gate epilogue
#pragma unroll
        for (int i = 0; i < 2; i++) {
            int rbase = m0 + wm * 32 + i * 16 + (lane >> 2);
#pragma unroll
            for (int e = 0; e < 4; e++) {
                int bb = rbase + ((e >> 1) << 3);
                int hc = cbase + (e & 1);
                float m = g_mask[bb * TT + t];
                float ghr = acc[0][i][e] * m + bias_r[e & 1];
                float ghz = acc[1][i][e] * m + bias_z[e & 1];
                float ghn = acc[2][i][e] * m + bias_n[e & 1];
                const float* gi = g_gi + ((size_t)bb * TT + t) * GG + hc;
                float r = sigmoidf_(gi[0] + ghr);
                float z = sigmoidf_(gi[1024] + ghz);
                float n = tanhf(gi[2048] + r * ghn);
                float hp = g_h[cur][bb * HH + hc];
                float hn2 = (1.f - z) * n + z * (m * hp);
                int idx = bb * HH + hc;
                g_h[nxt][idx] = hn2;
                bf16 hhi = __float2bfloat16(hn2);
                g_hhi[nxt][idx] = hhi;
                g_hlo[nxt][idx] = __float2bfloat16(hn2 - __bfloat162float(hhi));
                hseq_out[((size_t)bb * TT + t) * HH + hc] = hn2;
            }
        }

        grid_sync_();
    }
}

// ---------------- LayerNorm + gated residual ----------------
__device__ __forceinline__ float block_sum(float v, float* red) {
#pragma unroll
    for (int o = 16; o; o >>= 1) v += __shfl_xor_sync(0xffffffffu, v, o);
    int w = threadIdx.x >> 5;
    if ((threadIdx.x & 31) == 0) red[w] = v;
    __syncthreads();
    if (threadIdx.x < 32) {
        float r = (threadIdx.x < 8) ? red[threadIdx.x] : 0.f;
#pragma unroll
        for (int o = 4; o; o >>= 1) r += __shfl_xor_sync(0xffffffffu, r, o);
        if (threadIdx.x == 0) red[0] = r;
    }
    __syncthreads();
    float out = red[0];
    __syncthreads();
    return out;
}

__global__ __launch_bounds__(256) void ln_kernel(const float* __restrict__ x,
                                                 const float* __restrict__ ln_g,
                                                 const float* __restrict__ ln_b,
                                                 const float* __restrict__ res_gate,
                                                 const float* __restrict__ hseq,
                                                 float* __restrict__ y) {
    __shared__ float red[8];
    int row = blockIdx.x;
    int tid = threadIdx.x;
    const float* hr = hseq + (size_t)row * HH;
    float v[4];
    float s = 0.f;
#pragma unroll
    for (int j = 0; j < 4; j++) { v[j] = hr[tid + j * 256]; s += v[j]; }
    float mu = block_sum(s, red) * (1.f / HH);
    float s2 = 0.f;
#pragma unroll
    for (int j = 0; j < 4; j++) { float d = v[j] - mu; s2 += d * d; }
    float var = block_sum(s2, red) * (1.f / HH);
    float rstd = rsqrtf(var + 1e-5f);
#pragma unroll
    for (int j = 0; j < 4; j++) {
        int hc = tid + j * 256;
        float gate = 1.f / (1.f + expf(-res_gate[hc]));
        y[(size_t)row * HH + hc] =
            (v[j] - mu) * rstd * ln_g[hc] + ln_b[hc] + x[(size_t)row * HH + hc] * gate;
    }
}

// ---------------- launch ----------------
extern "C" void kernel_launch(void* const* d_in, const int* in_sizes, int n_in,
                              void* d_out, int out_size) {
    const float* x        = (const float*)d_in[0];
    const float* hx       = (const float*)d_in[1];
    const void*  isin     = d_in[2];
    const float* W_ih     = (const float*)d_in[3];
    const float* W_hh     = (const float*)d_in[4];
    const float* b_ih     = (const float*)d_in[5];
    const float* b_hh     = (const float*)d_in[6];
    const float* ln_g     = (const float*)d_in[7];
    const float* ln_b     = (const float*)d_in[8];
    const float* res_gate = (const float*)d_in[9];
    float* out  = (float*)d_out;
    float* Y    = out;
    float* Hseq = out + (size_t)BT * HH;

    mask_kernel<<<32, 256>>>(isin);
    split_x_kernel<<<2048, 256>>>(x);
    split_wih_kernel<<<512, 256>>>(W_ih);
    split_whh_kernel<<<512, 256>>>(W_hh);
    init_h_kernel<<<256, 256>>>(hx);

    dim3 g1(GG / 64, BT / 128);
    gi_gemm<<<g1, 256>>>(b_ih);

    dim3 g2(HH / 32, BATCH / 64);  // 32 x 4 = 128 blocks, one resident wave
    gru_scan<<<g2, 256>>>(b_hh, Hseq);

    ln_kernel<<<BT, 256>>>(x, ln_g, ln_b, res_gate, Hseq, Y);
}

// round 7
// speedup vs baseline: 1.0110x; 1.0110x over previous
#include <cuda_runtime.h>
#include <cuda_bf16.h>
#include <cstdint>
#include <cstddef>

typedef __nv_bfloat16 bf16;

#define BATCH 256
#define TT    128
#define DD    1024
#define HH    1024
#define GG    3072
#define BT    (BATCH*TT)   // 32768
#define SCAN_BLOCKS 128

// ---------------- device scratch (static; no runtime allocation) ----------------
__device__ float g_gi[(size_t)BT * GG];                 // 402 MB
__device__ bf16  g_xhi[(size_t)BT * DD];
__device__ bf16  g_xlo[(size_t)BT * DD];
__device__ bf16  g_wih_hi[(size_t)GG * DD];
__device__ bf16  g_wih_lo[(size_t)GG * DD];
__device__ bf16  g_whh_hi[(size_t)GG * HH];
__device__ bf16  g_whh_lo[(size_t)GG * HH];
__device__ float g_h[2][BATCH * HH];
__device__ bf16  g_hhi[2][BATCH * HH];
__device__ bf16  g_hlo[2][BATCH * HH];
__device__ float g_mask[BT];
__device__ unsigned g_bar_arrive;   // zero-init; self-restoring
__device__ unsigned g_bar_gen;      // monotonically increasing across replays (equality-compared)

// ---------------- helpers ----------------
__device__ __forceinline__ void cp16(uint32_t dst, const void* src) {
    asm volatile("cp.async.cg.shared.global [%0], [%1], 16;\n" :: "r"(dst), "l"(src));
}
__device__ __forceinline__ void cp_commit() { asm volatile("cp.async.commit_group;\n"); }
template<int N> __device__ __forceinline__ void cp_wait() {
    asm volatile("cp.async.wait_group %0;\n" :: "n"(N));
}
__device__ __forceinline__ void ldm4(uint32_t* r, uint32_t a) {
    asm volatile("ldmatrix.sync.aligned.m8n8.x4.shared.b16 {%0,%1,%2,%3},[%4];\n"
                 : "=r"(r[0]), "=r"(r[1]), "=r"(r[2]), "=r"(r[3]) : "r"(a));
}
__device__ __forceinline__ void ldm2(uint32_t* r, uint32_t a) {
    asm volatile("ldmatrix.sync.aligned.m8n8.x2.shared.b16 {%0,%1},[%2];\n"
                 : "=r"(r[0]), "=r"(r[1]) : "r"(a));
}
__device__ __forceinline__ void mma16816(float* c, const uint32_t* a, const uint32_t* b) {
    asm volatile("mma.sync.aligned.m16n8k16.row.col.f32.bf16.bf16.f32 "
                 "{%0,%1,%2,%3},{%4,%5,%6,%7},{%8,%9},{%0,%1,%2,%3};\n"
                 : "+f"(c[0]), "+f"(c[1]), "+f"(c[2]), "+f"(c[3])
                 : "r"(a[0]), "r"(a[1]), "r"(a[2]), "r"(a[3]), "r"(b[0]), "r"(b[1]));
}
// smem rows are 64B (32 halves); chunk = 16B unit; XOR swizzle on (row&3)
__device__ __forceinline__ uint32_t sw(uint32_t base, int r, int c) {
    return base + (r << 6) + ((c ^ (r & 3)) << 4);
}
__device__ __forceinline__ float sigmoidf_(float x) { return 1.f / (1.f + expf(-x)); }

// GPU-wide barrier (all SCAN_BLOCKS blocks resident; one wave guaranteed).
__device__ __forceinline__ void grid_sync_() {
    __threadfence();
    __syncthreads();
    if (threadIdx.x == 0) {
        unsigned gen;
        asm volatile("ld.acquire.gpu.u32 %0, [%1];" : "=r"(gen) : "l"(&g_bar_gen));
        unsigned ticket = atomicAdd(&g_bar_arrive, 1u);
        if (ticket == SCAN_BLOCKS - 1u) {
            g_bar_arrive = 0u;
            __threadfence();
            atomicAdd(&g_bar_gen, 1u);
        } else {
            unsigned cur;
            do {
                asm volatile("ld.acquire.gpu.u32 %0, [%1];" : "=r"(cur) : "l"(&g_bar_gen));
            } while (cur == gen);
        }
    }
    __syncthreads();
}

// ---------------- prep kernels ----------------
__global__ void mask_kernel(const void* __restrict__ isin) {
    __shared__ int is32;
    if (threadIdx.x == 0) {
        const unsigned char* p = (const unsigned char*)isin;
        int ok = 1;
        for (int i = 0; i < 1024; i++) {
            if (p[4 * i + 1] | p[4 * i + 2] | p[4 * i + 3]) { ok = 0; break; }
        }
        is32 = ok;
    }
    __syncthreads();
    int start = blockIdx.x * blockDim.x + threadIdx.x;
    int stride = gridDim.x * blockDim.x;
    if (is32) {
        const int* q = (const int*)isin;
        for (int i = start; i < BT; i += stride) g_mask[i] = q[i] ? 0.f : 1.f;
    } else {
        const unsigned char* q = (const unsigned char*)isin;
        for (int i = start; i < BT; i += stride) g_mask[i] = q[i] ? 0.f : 1.f;
    }
}

__global__ void split_x_kernel(const float* __restrict__ x) {
    size_t n = (size_t)BT * DD;
    for (size_t i = blockIdx.x * (size_t)blockDim.x + threadIdx.x; i < n;
         i += (size_t)gridDim.x * blockDim.x) {
        float f = x[i];
        bf16 h = __float2bfloat16(f);
        g_xhi[i] = h;
        g_xlo[i] = __float2bfloat16(f - __bfloat162float(h));
    }
}
__global__ void split_wih_kernel(const float* __restrict__ w) {
    size_t n = (size_t)GG * DD;
    for (size_t i = blockIdx.x * (size_t)blockDim.x + threadIdx.x; i < n;
         i += (size_t)gridDim.x * blockDim.x) {
        float f = w[i];
        bf16 h = __float2bfloat16(f);
        g_wih_hi[i] = h;
        g_wih_lo[i] = __float2bfloat16(f - __bfloat162float(h));
    }
}
__global__ void split_whh_kernel(const float* __restrict__ w) {
    size_t n = (size_t)GG * HH;
    for (size_t i = blockIdx.x * (size_t)blockDim.x + threadIdx.x; i < n;
         i += (size_t)gridDim.x * blockDim.x) {
        float f = w[i];
        bf16 h = __float2bfloat16(f);
        g_whh_hi[i] = h;
        g_whh_lo[i] = __float2bfloat16(f - __bfloat162float(h));
    }
}
__global__ void init_h_kernel(const float* __restrict__ hx) {
    int n = BATCH * HH;
    for (int i = blockIdx.x * blockDim.x + threadIdx.x; i < n; i += gridDim.x * blockDim.x) {
        float f = hx[i];
        g_h[0][i] = f;
        bf16 h = __float2bfloat16(f);
        g_hhi[0][i] = h;
        g_hlo[0][i] = __float2bfloat16(f - __bfloat162float(h));
    }
}

// ---------------- gi = x @ W_ih^T + b_ih (split-bf16, 3-MMA) ----------------
// grid (GG/64, BT/128), block 256
__global__ __launch_bounds__(256) void gi_gemm(const float* __restrict__ b_ih) {
    __shared__ __align__(16) char smem[49152];
    uint32_t sb = (uint32_t)__cvta_generic_to_shared(smem);
    int tid = threadIdx.x, lane = tid & 31, w = tid >> 5;
    int wm = w & 3, wn = w >> 2;
    int m0 = blockIdx.y * 128, n0 = blockIdx.x * 64;

    float acc[2][4][4];
#pragma unroll
    for (int i = 0; i < 2; i++)
#pragma unroll
        for (int j = 0; j < 4; j++)
#pragma unroll
            for (int e = 0; e < 4; e++) acc[i][j][e] = 0.f;

    auto load_stage = [&](int kt, int s) {
        uint32_t o = sb + s * 24576;
        int k0 = kt * 32;
#pragma unroll
        for (int v = tid; v < 512; v += 256) {
            int r = v >> 2, c = v & 3;
            const bf16* sh = g_xhi + (size_t)(m0 + r) * DD + k0 + c * 8;
            const bf16* sl = g_xlo + (size_t)(m0 + r) * DD + k0 + c * 8;
            cp16(sw(o, r, c), sh);
            cp16(sw(o + 8192, r, c), sl);
        }
        {
            int v = tid;
            int r = v >> 2, c = v & 3;
            cp16(sw(o + 16384, r, c), g_wih_hi + (size_t)(n0 + r) * DD + k0 + c * 8);
            cp16(sw(o + 20480, r, c), g_wih_lo + (size_t)(n0 + r) * DD + k0 + c * 8);
        }
        cp_commit();
    };

    load_stage(0, 0);
    const int KT = DD / 32;
    for (int kt = 0; kt < KT; kt++) {
        if (kt + 1 < KT) load_stage(kt + 1, (kt + 1) & 1);
        if (kt + 1 < KT) cp_wait<1>(); else cp_wait<0>();
        __syncthreads();
        uint32_t o = sb + (kt & 1) * 24576;
#pragma unroll
        for (int kk = 0; kk < 2; kk++) {
            uint32_t ah[2][4], al[2][4], bh[4][2], bl[4][2];
#pragma unroll
            for (int i = 0; i < 2; i++) {
                int r = wm * 32 + i * 16 + (lane & 15);
                int c = kk * 2 + (lane >> 4);
                ldm4(ah[i], sw(o, r, c));
                ldm4(al[i], sw(o + 8192, r, c));
            }
#pragma unroll
            for (int sg = 0; sg < 2; sg++) {
                int r = wn * 32 + sg * 16 + ((lane >> 4) & 1) * 8 + (lane & 7);
                int c = kk * 2 + ((lane >> 3) & 1);
                uint32_t t4[4];
                ldm4(t4, sw(o + 16384, r, c));
                bh[sg * 2][0] = t4[0]; bh[sg * 2][1] = t4[1];
                bh[sg * 2 + 1][0] = t4[2]; bh[sg * 2 + 1][1] = t4[3];
                ldm4(t4, sw(o + 20480, r, c));
                bl[sg * 2][0] = t4[0]; bl[sg * 2][1] = t4[1];
                bl[sg * 2 + 1][0] = t4[2]; bl[sg * 2 + 1][1] = t4[3];
            }
#pragma unroll
            for (int i = 0; i < 2; i++)
#pragma unroll
                for (int j = 0; j < 4; j++) {
                    mma16816(acc[i][j], ah[i], bh[j]);
                    mma16816(acc[i][j], ah[i], bl[j]);
                    mma16816(acc[i][j], al[i], bh[j]);
                }
        }
        __syncthreads();
    }

#pragma unroll
    for (int i = 0; i < 2; i++) {
        int row = m0 + wm * 32 + i * 16 + (lane >> 2);
#pragma unroll
        for (int j = 0; j < 4; j++) {
            int col = n0 + wn * 32 + j * 8 + (lane & 3) * 2;
            float b0 = b_ih[col], b1 = b_ih[col + 1];
            g_gi[(size_t)row * GG + col]           = acc[i][j][0] + b0;
            g_gi[(size_t)row * GG + col + 1]       = acc[i][j][1] + b1;
            g_gi[(size_t)(row + 8) * GG + col]     = acc[i][j][2] + b0;
            g_gi[(size_t)(row + 8) * GG + col + 1] = acc[i][j][3] + b1;
        }
    }
}

// ---------------- persistent GRU scan: 128 steps in one kernel ----------------
// grid (HH/32, BATCH/64) = (32,4) = 128 blocks, block 256
__global__ __launch_bounds__(256) void gru_scan(const float* __restrict__ b_hh,
                                                float* __restrict__ hseq_out) {
    __shared__ __align__(16) char smem[40960];
    uint32_t sb = (uint32_t)__cvta_generic_to_shared(smem);
    int tid = threadIdx.x, lane = tid & 31, w = tid >> 5;
    int wm = w & 1, wn = w >> 1;
    int m0 = blockIdx.y * 64, n0 = blockIdx.x * 32;

    // hoist per-thread gate biases (epilogue columns are t-invariant)
    int cbase = n0 + wn * 8 + (lane & 3) * 2;
    float bias_r[2], bias_z[2], bias_n[2];
#pragma unroll
    for (int e = 0; e < 2; e++) {
        bias_r[e] = b_hh[cbase + e];
        bias_z[e] = b_hh[1024 + cbase + e];
        bias_n[e] = b_hh[2048 + cbase + e];
    }

    for (int t = 0; t < TT; t++) {
        int cur = t & 1, nxt = cur ^ 1;

        float acc[3][2][4];
#pragma unroll
        for (int g = 0; g < 3; g++)
#pragma unroll
            for (int i = 0; i < 2; i++)
#pragma unroll
                for (int e = 0; e < 4; e++) acc[g][i][e] = 0.f;

        auto load_stage = [&](int kt, int s) {
            uint32_t o = sb + s * 20480;
            int k0 = kt * 32;
            {
                int v = tid;  // 64 rows x 4 chunks = 256 exactly
                int r = v >> 2, c = v & 3;
                cp16(sw(o, r, c), g_hhi[cur] + (size_t)(m0 + r) * HH + k0 + c * 8);
                cp16(sw(o + 4096, r, c), g_hlo[cur] + (size_t)(m0 + r) * HH + k0 + c * 8);
            }
#pragma unroll
            for (int v = tid; v < 384; v += 256) {  // 96 rows x 4 chunks
                int r = v >> 2, c = v & 3;
                size_t grow = (size_t)((r >> 5) * HH + n0 + (r & 31));
                cp16(sw(o + 8192, r, c), g_whh_hi + grow * HH + k0 + c * 8);
                cp16(sw(o + 14336, r, c), g_whh_lo + grow * HH + k0 + c * 8);
            }
            cp_commit();
        };

        load_stage(0, 0);
        const int KT = HH / 32;
        for (int kt = 0; kt < KT; kt++) {
            if (kt + 1 < KT) load_stage(kt + 1, (kt + 1) & 1);
            if (kt + 1 < KT) cp_wait<1>(); else cp_wait<0>();
            __syncthreads();
            uint32_t o = sb + (kt & 1) * 20480;
#pragma unroll
            for (int kk = 0; kk < 2; kk++) {
                uint32_t ah[2][4], al[2][4], bh[3][2], bl[3][2];
#pragma unroll
                for (int i = 0; i < 2; i++) {
                    int r = wm * 32 + i * 16 + (lane & 15);
                    int c = kk * 2 + (lane >> 4);
                    ldm4(ah[i], sw(o, r, c));
                    ldm4(al[i], sw(o + 4096, r, c));
                }
#pragma unroll
                for (int g = 0; g < 3; g++) {
                    int l = lane & 15;
                    int r = g * 32 + wn * 8 + (l & 7);
                    int c = kk * 2 + (l >> 3);
                    ldm2(bh[g], sw(o + 8192, r, c));
                    ldm2(bl[g], sw(o + 14336, r, c));
                }
#pragma unroll
                for (int g = 0; g < 3; g++)
#pragma unroll
                    for (int i = 0; i < 2; i++) {
                        mma16816(acc[g][i], ah[i], bh[g]);
                        mma16816(acc[g][i], ah[i], bl[g]);
                        mma16816(acc[g][i], al[i], bh[g]);
                    }
            }
            __syncthreads();
        }

        // fused gate epilogue
#pragma unroll
        for (int i = 0; i < 2; i++) {
            int rbase = m0 + wm * 32 + i * 16 + (lane >> 2);
#pragma unroll
            for (int e = 0; e < 4; e++) {
                int bb = rbase + ((e >> 1) << 3);
                int hc = cbase + (e & 1);
                float m = g_mask[bb * TT + t];
                float ghr = acc[0][i][e] * m + bias_r[e & 1];
                float ghz = acc[1][i][e] * m + bias_z[e & 1];
                float ghn = acc[2][i][e] * m + bias_n[e & 1];
                const float* gi = g_gi + ((size_t)bb * TT + t) * GG + hc;
                float r = sigmoidf_(gi[0] + ghr);
                float z = sigmoidf_(gi[1024] + ghz);
                float n = tanhf(gi[2048] + r * ghn);
                float hp = g_h[cur][bb * HH + hc];
                float hn2 = (1.f - z) * n + z * (m * hp);
                int idx = bb * HH + hc;
                g_h[nxt][idx] = hn2;
                bf16 hhi = __float2bfloat16(hn2);
                g_hhi[nxt][idx] = hhi;
                g_hlo[nxt][idx] = __float2bfloat16(hn2 - __bfloat162float(hhi));
                hseq_out[((size_t)bb * TT + t) * HH + hc] = hn2;
            }
        }

        grid_sync_();
    }
}

// ---------------- LayerNorm + gated residual ----------------
__device__ __forceinline__ float block_sum(float v, float* red) {
#pragma unroll
    for (int o = 16; o; o >>= 1) v += __shfl_xor_sync(0xffffffffu, v, o);
    int w = threadIdx.x >> 5;
    if ((threadIdx.x & 31) == 0) red[w] = v;
    __syncthreads();
    if (threadIdx.x < 32) {
        float r = (threadIdx.x < 8) ? red[threadIdx.x] : 0.f;
#pragma unroll
        for (int o = 4; o; o >>= 1) r += __shfl_xor_sync(0xffffffffu, r, o);
        if (threadIdx.x == 0) red[0] = r;
    }
    __syncthreads();
    float out = red[0];
    __syncthreads();
    return out;
}

__global__ __launch_bounds__(256) void ln_kernel(const float* __restrict__ x,
                                                 const float* __restrict__ ln_g,
                                                 const float* __restrict__ ln_b,
                                                 const float* __restrict__ res_gate,
                                                 const float* __restrict__ hseq,
                                                 float* __restrict__ y) {
    __shared__ float red[8];
    int row = blockIdx.x;
    int tid = threadIdx.x;
    const float* hr = hseq + (size_t)row * HH;
    float v[4];
    float s = 0.f;
#pragma unroll
    for (int j = 0; j < 4; j++) { v[j] = hr[tid + j * 256]; s += v[j]; }
    float mu = block_sum(s, red) * (1.f / HH);
    float s2 = 0.f;
#pragma unroll
    for (int j = 0; j < 4; j++) { float d = v[j] - mu; s2 += d * d; }
    float var = block_sum(s2, red) * (1.f / HH);
    float rstd = rsqrtf(var + 1e-5f);
#pragma unroll
    for (int j = 0; j < 4; j++) {
        int hc = tid + j * 256;
        float gate = 1.f / (1.f + expf(-res_gate[hc]));
        y[(size_t)row * HH + hc] =
            (v[j] - mu) * rstd * ln_g[hc] + ln_b[hc] + x[(size_t)row * HH + hc] * gate;
    }
}

// ---------------- launch ----------------
extern "C" void kernel_launch(void* const* d_in, const int* in_sizes, int n_in,
                              void* d_out, int out_size) {
    const float* x        = (const float*)d_in[0];
    const float* hx       = (const float*)d_in[1];
    const void*  isin     = d_in[2];
    const float* W_ih     = (const float*)d_in[3];
    const float* W_hh     = (const float*)d_in[4];
    const float* b_ih     = (const float*)d_in[5];
    const float* b_hh     = (const float*)d_in[6];
    const float* ln_g     = (const float*)d_in[7];
    const float* ln_b     = (const float*)d_in[8];
    const float* res_gate = (const float*)d_in[9];
    float* out  = (float*)d_out;
    float* Y    = out;
    float* Hseq = out + (size_t)BT * HH;

    mask_kernel<<<32, 256>>>(isin);
    split_x_kernel<<<2048, 256>>>(x);
    split_wih_kernel<<<512, 256>>>(W_ih);
    split_whh_kernel<<<512, 256>>>(W_hh);
    init_h_kernel<<<256, 256>>>(hx);

    dim3 g1(GG / 64, BT / 128);
    gi_gemm<<<g1, 256>>>(b_ih);

    dim3 g2(HH / 32, BATCH / 64);  // 32 x 4 = 128 blocks, one resident wave
    gru_scan<<<g2, 256>>>(b_hh, Hseq);

    ln_kernel<<<BT, 256>>>(x, ln_g, ln_b, res_gate, Hseq, Y);
}

// round 9
// speedup vs baseline: 1.2042x; 1.1912x over previous
#include <cuda_runtime.h>
#include <cuda_bf16.h>
#include <cstdint>
#include <cstddef>

typedef __nv_bfloat16 bf16;

#define BATCH 256
#define TT    128
#define DD    1024
#define HH    1024
#define GG    3072
#define BT    (BATCH*TT)
#define SCAN_BLOCKS 128

#define SC_STAGE 40960
#define SC_NS    3
#define SC_SMEM  (SC_NS*SC_STAGE)   // 122880 bytes dynamic

// ---------------- device scratch (static; no runtime allocation) ----------------
__device__ float g_gi[(size_t)BT * GG];
__device__ bf16  g_xhi[(size_t)BT * DD];
__device__ bf16  g_xlo[(size_t)BT * DD];
__device__ bf16  g_wih_hi[(size_t)GG * DD];
__device__ bf16  g_wih_lo[(size_t)GG * DD];
__device__ bf16  g_whh_hi[(size_t)GG * HH];
__device__ bf16  g_whh_lo[(size_t)GG * HH];
__device__ float g_h[2][BATCH * HH];
__device__ bf16  g_hhi[2][BATCH * HH];
__device__ bf16  g_hlo[2][BATCH * HH];
__device__ float g_mask[BT];
__device__ unsigned g_bar_arrive;   // zero-init; drains back to 0 (replay-safe)
__device__ unsigned g_bar_gen;      // monotonic; equality-compared

// ---------------- helpers ----------------
__device__ __forceinline__ void cp16(uint32_t dst, const void* src) {
    asm volatile("cp.async.cg.shared.global [%0], [%1], 16;\n" :: "r"(dst), "l"(src));
}
__device__ __forceinline__ void cp_commit() { asm volatile("cp.async.commit_group;\n"); }
template<int N> __device__ __forceinline__ void cp_wait() {
    asm volatile("cp.async.wait_group %0;\n" :: "n"(N));
}
__device__ __forceinline__ void ldm4(uint32_t* r, uint32_t a) {
    asm volatile("ldmatrix.sync.aligned.m8n8.x4.shared.b16 {%0,%1,%2,%3},[%4];\n"
                 : "=r"(r[0]), "=r"(r[1]), "=r"(r[2]), "=r"(r[3]) : "r"(a));
}
__device__ __forceinline__ void mma16816(float* c, const uint32_t* a, const uint32_t* b) {
    asm volatile("mma.sync.aligned.m16n8k16.row.col.f32.bf16.bf16.f32 "
                 "{%0,%1,%2,%3},{%4,%5,%6,%7},{%8,%9},{%0,%1,%2,%3};\n"
                 : "+f"(c[0]), "+f"(c[1]), "+f"(c[2]), "+f"(c[3])
                 : "r"(a[0]), "r"(a[1]), "r"(a[2]), "r"(a[3]), "r"(b[0]), "r"(b[1]));
}
// 64B-row swizzle (gi kernel): chunk 0..3, XOR row&3
__device__ __forceinline__ uint32_t sw(uint32_t base, int r, int c) {
    return base + (r << 6) + ((c ^ (r & 3)) << 4);
}
// 128B-row swizzle (scan): chunk 0..7, XOR row&7 -> conflict-free LDSM
__device__ __forceinline__ uint32_t sw128(uint32_t base, int r, int c) {
    return base + ((uint32_t)r << 7) + ((uint32_t)((c ^ (r & 7)) & 7) << 4);
}
__device__ __forceinline__ float sigmoidf_(float x) { return 1.f / (1.f + expf(-x)); }

// GPU-wide barrier (SCAN_BLOCKS resident blocks; one wave guaranteed).
__device__ __forceinline__ void grid_sync_() {
    __threadfence();
    __syncthreads();
    if (threadIdx.x == 0) {
        unsigned gen;
        asm volatile("ld.acquire.gpu.u32 %0, [%1];" : "=r"(gen) : "l"(&g_bar_gen));
        unsigned ticket = atomicAdd(&g_bar_arrive, 1u);
        if (ticket == SCAN_BLOCKS - 1u) {
            g_bar_arrive = 0u;
            __threadfence();
            atomicAdd(&g_bar_gen, 1u);
        } else {
            unsigned cur;
            do {
                asm volatile("ld.acquire.gpu.u32 %0, [%1];" : "=r"(cur) : "l"(&g_bar_gen));
            } while (cur == gen);
        }
    }
    __syncthreads();
}

// ---------------- prep kernels ----------------
__global__ void mask_kernel(const void* __restrict__ isin) {
    __shared__ int is32;
    if (threadIdx.x == 0) {
        const unsigned char* p = (const unsigned char*)isin;
        int ok = 1;
        for (int i = 0; i < 1024; i++)
            if (p[4 * i + 1] | p[4 * i + 2] | p[4 * i + 3]) { ok = 0; break; }
        is32 = ok;
    }
    __syncthreads();
    int start = blockIdx.x * blockDim.x + threadIdx.x;
    int stride = gridDim.x * blockDim.x;
    if (is32) {
        const int* q = (const int*)isin;
        for (int i = start; i < BT; i += stride) g_mask[i] = q[i] ? 0.f : 1.f;
    } else {
        const unsigned char* q = (const unsigned char*)isin;
        for (int i = start; i < BT; i += stride) g_mask[i] = q[i] ? 0.f : 1.f;
    }
}
__global__ void split_x_kernel(const float* __restrict__ x) {
    size_t n = (size_t)BT * DD;
    for (size_t i = blockIdx.x * (size_t)blockDim.x + threadIdx.x; i < n;
         i += (size_t)gridDim.x * blockDim.x) {
        float f = x[i];
        bf16 h = __float2bfloat16(f);
        g_xhi[i] = h;
        g_xlo[i] = __float2bfloat16(f - __bfloat162float(h));
    }
}
__global__ void split_w_kernel(const float* __restrict__ wih, const float* __restrict__ whh) {
    size_t n = (size_t)GG * DD;
    for (size_t i = blockIdx.x * (size_t)blockDim.x + threadIdx.x; i < n;
         i += (size_t)gridDim.x * blockDim.x) {
        float f = wih[i];
        bf16 h = __float2bfloat16(f);
        g_wih_hi[i] = h;
        g_wih_lo[i] = __float2bfloat16(f - __bfloat162float(h));
        float g = whh[i];
        bf16 hh = __float2bfloat16(g);
        g_whh_hi[i] = hh;
        g_whh_lo[i] = __float2bfloat16(g - __bfloat162float(hh));
    }
}
__global__ void init_h_kernel(const float* __restrict__ hx) {
    int n = BATCH * HH;
    for (int i = blockIdx.x * blockDim.x + threadIdx.x; i < n; i += gridDim.x * blockDim.x) {
        float f = hx[i];
        g_h[0][i] = f;
        bf16 h = __float2bfloat16(f);
        g_hhi[0][i] = h;
        g_hlo[0][i] = __float2bfloat16(f - __bfloat162float(h));
    }
}

// ---------------- gi = x @ W_ih^T + b_ih (split-bf16, 3-MMA, legacy mma) ----------------
// grid (GG/64, BT/128), block 256
__global__ __launch_bounds__(256) void gi_gemm(const float* __restrict__ b_ih) {
    __shared__ __align__(16) char smem[49152];
    uint32_t sb = (uint32_t)__cvta_generic_to_shared(smem);
    int tid = threadIdx.x, lane = tid & 31, w = tid >> 5;
    int wm = w & 3, wn = w >> 2;
    int m0 = blockIdx.y * 128, n0 = blockIdx.x * 64;

    float acc[2][4][4];
#pragma unroll
    for (int i = 0; i < 2; i++)
#pragma unroll
        for (int j = 0; j < 4; j++)
#pragma unroll
            for (int e = 0; e < 4; e++) acc[i][j][e] = 0.f;

    auto load_stage = [&](int kt, int s) {
        uint32_t o = sb + s * 24576;
        int k0 = kt * 32;
#pragma unroll
        for (int v = tid; v < 512; v += 256) {
            int r = v >> 2, c = v & 3;
            const bf16* sh = g_xhi + (size_t)(m0 + r) * DD + k0 + c * 8;
            const bf16* sl = g_xlo + (size_t)(m0 + r) * DD + k0 + c * 8;
            cp16(sw(o, r, c), sh);
            cp16(sw(o + 8192, r, c), sl);
        }
        {
            int v = tid;
            int r = v >> 2, c = v & 3;
            cp16(sw(o + 16384, r, c), g_wih_hi + (size_t)(n0 + r) * DD + k0 + c * 8);
            cp16(sw(o + 20480, r, c), g_wih_lo + (size_t)(n0 + r) * DD + k0 + c * 8);
        }
        cp_commit();
    };

    load_stage(0, 0);
    const int KT = DD / 32;
    for (int kt = 0; kt < KT; kt++) {
        if (kt + 1 < KT) load_stage(kt + 1, (kt + 1) & 1);
        if (kt + 1 < KT) cp_wait<1>(); else cp_wait<0>();
        __syncthreads();
        uint32_t o = sb + (kt & 1) * 24576;
#pragma unroll
        for (int kk = 0; kk < 2; kk++) {
            uint32_t ah[2][4], al[2][4], bh[4][2], bl[4][2];
#pragma unroll
            for (int i = 0; i < 2; i++) {
                int r = wm * 32 + i * 16 + (lane & 15);
                int c = kk * 2 + (lane >> 4);
                ldm4(ah[i], sw(o, r, c));
                ldm4(al[i], sw(o + 8192, r, c));
            }
#pragma unroll
            for (int sg = 0; sg < 2; sg++) {
                int r = wn * 32 + sg * 16 + ((lane >> 4) & 1) * 8 + (lane & 7);
                int c = kk * 2 + ((lane >> 3) & 1);
                uint32_t t4[4];
                ldm4(t4, sw(o + 16384, r, c));
                bh[sg * 2][0] = t4[0]; bh[sg * 2][1] = t4[1];
                bh[sg * 2 + 1][0] = t4[2]; bh[sg * 2 + 1][1] = t4[3];
                ldm4(t4, sw(o + 20480, r, c));
                bl[sg * 2][0] = t4[0]; bl[sg * 2][1] = t4[1];
                bl[sg * 2 + 1][0] = t4[2]; bl[sg * 2 + 1][1] = t4[3];
            }
#pragma unroll
            for (int i = 0; i < 2; i++)
#pragma unroll
                for (int j = 0; j < 4; j++) {
                    mma16816(acc[i][j], ah[i], bh[j]);
                    mma16816(acc[i][j], ah[i], bl[j]);
                    mma16816(acc[i][j], al[i], bh[j]);
                }
        }
        __syncthreads();
    }

#pragma unroll
    for (int i = 0; i < 2; i++) {
        int row = m0 + wm * 32 + i * 16 + (lane >> 2);
#pragma unroll
        for (int j = 0; j < 4; j++) {
            int col = n0 + wn * 32 + j * 8 + (lane & 3) * 2;
            float b0 = b_ih[col], b1 = b_ih[col + 1];
            g_gi[(size_t)row * GG + col]           = acc[i][j][0] + b0;
            g_gi[(size_t)row * GG + col + 1]       = acc[i][j][1] + b1;
            g_gi[(size_t)(row + 8) * GG + col]     = acc[i][j][2] + b0;
            g_gi[(size_t)(row + 8) * GG + col + 1] = acc[i][j][3] + b1;
        }
    }
}

// ---------------- persistent GRU scan: K64 chunks, 3-stage ring, W-prefetch over barrier ----
// grid (HH/32=32, BATCH/64=4) = 128 blocks, block 256 (8 warps: wm 2 x wn 4)
// stage layout: A_hi 0 (64x128B), A_lo +8192, B_hi +16384 (96x128B), B_lo +28672
__global__ __launch_bounds__(256, 1) void gru_scan(const float* __restrict__ b_hh,
                                                   float* __restrict__ hseq_out) {
    extern __shared__ __align__(128) char smem_dyn[];
    uint32_t sb = (uint32_t)__cvta_generic_to_shared(smem_dyn);
    int tid = threadIdx.x, lane = tid & 31, w = tid >> 5;
    int wm = w & 1, wn = w >> 1;
    int m0 = blockIdx.y * 64, n0 = blockIdx.x * 32;

    // hoisted per-thread gate biases (t-invariant epilogue columns)
    int cbase = n0 + wn * 8 + (lane & 3) * 2;
    float bias_r[2], bias_z[2], bias_n[2];
#pragma unroll
    for (int e = 0; e < 2; e++) {
        bias_r[e] = b_hh[cbase + e];
        bias_z[e] = b_hh[1024 + cbase + e];
        bias_n[e] = b_hh[2048 + cbase + e];
    }

    auto loadB = [&](int kc, int s) {   // W_hh chunk (t-invariant), no commit
        uint32_t o = sb + (uint32_t)s * SC_STAGE;
        int k0 = kc * 64;
#pragma unroll
        for (int v = tid; v < 768; v += 256) {       // 96 rows x 8 chunks
            int r = v >> 3, c = v & 7;
            size_t grow = (size_t)((r >> 5) * 1024 + n0 + (r & 31));
            size_t go = grow * HH + k0 + c * 8;
            cp16(sw128(o + 16384, r, c), g_whh_hi + go);
            cp16(sw128(o + 28672, r, c), g_whh_lo + go);
        }
    };
    auto loadA = [&](const bf16* Ahi, const bf16* Alo, int kc, int s) {  // h chunk, no commit
        uint32_t o = sb + (uint32_t)s * SC_STAGE;
        int k0 = kc * 64;
#pragma unroll
        for (int v = tid; v < 512; v += 256) {       // 64 rows x 8 chunks
            int r = v >> 3, c = v & 7;
            size_t go = (size_t)(m0 + r) * HH + k0 + c * 8;
            cp16(sw128(o, r, c), Ahi + go);
            cp16(sw128(o + 8192, r, c), Alo + go);
        }
    };

    // prologue: B chunks 0,1 for t=0 (uncommitted)
    loadB(0, 0);
    loadB(1, 1);

    for (int t = 0; t < TT; t++) {
        int cur = t & 1, nxt = cur ^ 1;
        const bf16* Ahi = g_hhi[cur];
        const bf16* Alo = g_hlo[cur];

        // commit group0 = {B(c0), B(c1), A(c0)}, group1 = {A(c1)}
        loadA(Ahi, Alo, 0, 0); cp_commit();
        loadA(Ahi, Alo, 1, 1); cp_commit();

        float acc[3][2][4];
#pragma unroll
        for (int g = 0; g < 3; g++)
#pragma unroll
            for (int i = 0; i < 2; i++)
#pragma unroll
                for (int e = 0; e < 4; e++) acc[g][i][e] = 0.f;

        for (int kt = 0; kt < 16; kt++) {
            // prefetch chunk kt+2 into stage (kt+2)%3 (freed at kt-1)
            if (kt <= 13) {
                int s = (kt + 2) % 3;
                loadB(kt + 2, s);
                loadA(Ahi, Alo, kt + 2, s);
                cp_commit();
            }
            if (kt <= 13) cp_wait<2>(); else if (kt == 14) cp_wait<1>(); else cp_wait<0>();
            __syncthreads();
            uint32_t o = sb + (uint32_t)(kt % 3) * SC_STAGE;
#pragma unroll
            for (int kk = 0; kk < 4; kk++) {
                uint32_t ah[2][4], al[2][4], b4[3][4];
#pragma unroll
                for (int i = 0; i < 2; i++) {
                    int r = wm * 32 + i * 16 + (lane & 15);
                    int c = kk * 2 + (lane >> 4);
                    ldm4(ah[i], sw128(o, r, c));
                    ldm4(al[i], sw128(o + 8192, r, c));
                }
#pragma unroll
                for (int g = 0; g < 3; g++) {
                    // lanes 0-15 -> B_hi tiles (2 k-halves), lanes 16-31 -> B_lo tiles
                    int r = g * 32 + wn * 8 + (lane & 7);
                    int c = kk * 2 + ((lane >> 3) & 1);
                    uint32_t bbase = (lane >= 16) ? (o + 28672) : (o + 16384);
                    ldm4(b4[g], sw128(bbase, r, c));
                }
#pragma unroll
                for (int g = 0; g < 3; g++)
#pragma unroll
                    for (int i = 0; i < 2; i++) {
                        mma16816(acc[g][i], ah[i], &b4[g][0]);   // hi*hi
                        mma16816(acc[g][i], ah[i], &b4[g][2]);   // hi*lo
                        mma16816(acc[g][i], al[i], &b4[g][0]);   // lo*hi
                    }
            }
            __syncthreads();
        }

        // prefetch next step's W chunks (t-invariant; independent of h writes)
        if (t + 1 < TT) {
            loadB(0, 0);
            loadB(1, 1);
        }

        // fused gate epilogue
#pragma unroll
        for (int i = 0; i < 2; i++) {
            int rbase = m0 + wm * 32 + i * 16 + (lane >> 2);
#pragma unroll
            for (int e = 0; e < 4; e++) {
                int bb = rbase + ((e >> 1) << 3);
                int hc = cbase + (e & 1);
                float m = g_mask[bb * TT + t];
                float ghr = acc[0][i][e] * m + bias_r[e & 1];
                float ghz = acc[1][i][e] * m + bias_z[e & 1];
                float ghn = acc[2][i][e] * m + bias_n[e & 1];
                const float* gi = g_gi + ((size_t)bb * TT + t) * GG + hc;
                float r = sigmoidf_(gi[0] + ghr);
                float z = sigmoidf_(gi[1024] + ghz);
                float n = tanhf(gi[2048] + r * ghn);
                float hp = g_h[cur][bb * HH + hc];
                float hn2 = (1.f - z) * n + z * (m * hp);
                int idx = bb * HH + hc;
                g_h[nxt][idx] = hn2;
                bf16 hhi = __float2bfloat16(hn2);
                g_hhi[nxt][idx] = hhi;
                g_hlo[nxt][idx] = __float2bfloat16(hn2 - __bfloat162float(hhi));
                hseq_out[((size_t)bb * TT + t) * HH + hc] = hn2;
            }
        }

        grid_sync_();
    }
}

// ---------------- LayerNorm + gated residual ----------------
__device__ __forceinline__ float block_sum(float v, float* red) {
#pragma unroll
    for (int o = 16; o; o >>= 1) v += __shfl_xor_sync(0xffffffffu, v, o);
    int w = threadIdx.x >> 5;
    if ((threadIdx.x & 31) == 0) red[w] = v;
    __syncthreads();
    if (threadIdx.x < 32) {
        float r = (threadIdx.x < 8) ? red[threadIdx.x] : 0.f;
#pragma unroll
        for (int o = 4; o; o >>= 1) r += __shfl_xor_sync(0xffffffffu, r, o);
        if (threadIdx.x == 0) red[0] = r;
    }
    __syncthreads();
    float out = red[0];
    __syncthreads();
    return out;
}

__global__ __launch_bounds__(256) void ln_kernel(const float* __restrict__ x,
                                                 const float* __restrict__ ln_g,
                                                 const float* __restrict__ ln_b,
                                                 const float* __restrict__ res_gate,
                                                 const float* __restrict__ hseq,
                                                 float* __restrict__ y) {
    __shared__ float red[8];
    int row = blockIdx.x;
    int tid = threadIdx.x;
    const float* hr = hseq + (size_t)row * HH;
    float v[4];
    float s = 0.f;
#pragma unroll
    for (int j = 0; j < 4; j++) { v[j] = hr[tid + j * 256]; s += v[j]; }
    float mu = block_sum(s, red) * (1.f / HH);
    float s2 = 0.f;
#pragma unroll
    for (int j = 0; j < 4; j++) { float d = v[j] - mu; s2 += d * d; }
    float var = block_sum(s2, red) * (1.f / HH);
    float rstd = rsqrtf(var + 1e-5f);
#pragma unroll
    for (int j = 0; j < 4; j++) {
        int hc = tid + j * 256;
        float gate = 1.f / (1.f + expf(-res_gate[hc]));
        y[(size_t)row * HH + hc] =
            (v[j] - mu) * rstd * ln_g[hc] + ln_b[hc] + x[(size_t)row * HH + hc] * gate;
    }
}

// ---------------- launch ----------------
extern "C" void kernel_launch(void* const* d_in, const int* in_sizes, int n_in,
                              void* d_out, int out_size) {
    const float* x        = (const float*)d_in[0];
    const float* hx       = (const float*)d_in[1];
    const void*  isin     = d_in[2];
    const float* W_ih     = (const float*)d_in[3];
    const float* W_hh     = (const float*)d_in[4];
    const float* b_ih     = (const float*)d_in[5];
    const float* b_hh     = (const float*)d_in[6];
    const float* ln_g     = (const float*)d_in[7];
    const float* ln_b     = (const float*)d_in[8];
    const float* res_gate = (const float*)d_in[9];
    float* out  = (float*)d_out;
    float* Y    = out;
    float* Hseq = out + (size_t)BT * HH;

    cudaFuncSetAttribute(gru_scan, cudaFuncAttributeMaxDynamicSharedMemorySize, SC_SMEM);

    // order chosen so gi_gemm is the 4th launch (ncu sampled slot)
    mask_kernel<<<32, 256>>>(isin);
    split_x_kernel<<<2048, 256>>>(x);
    split_w_kernel<<<1024, 256>>>(W_ih, W_hh);

    dim3 g1(GG / 64, BT / 128);
    gi_gemm<<<g1, 256>>>(b_ih);

    init_h_kernel<<<256, 256>>>(hx);

    dim3 g2(HH / 32, BATCH / 64);   // 32 x 4 = 128 persistent blocks
    gru_scan<<<g2, 256, SC_SMEM>>>(b_hh, Hseq);

    ln_kernel<<<BT, 256>>>(x, ln_g, ln_b, res_gate, Hseq, Y);
}

// round 10
// speedup vs baseline: 1.3112x; 1.0888x over previous
#include <cuda_runtime.h>
#include <cuda_bf16.h>
#include <cstdint>
#include <cstddef>

typedef __nv_bfloat16 bf16;

#define BATCH 256
#define TT    128
#define DD    1024
#define HH    1024
#define GG    3072
#define BT    (BATCH*TT)
#define SCAN_BLOCKS 128

#define GI_STAGE 65536
#define GI_NS    3
#define GI_SMEM  (GI_NS*GI_STAGE)   // 196608
#define SC_STAGE 40960
#define SC_NS    3
#define SC_SMEM  (SC_NS*SC_STAGE)   // 122880

// ---------------- device scratch (static; no runtime allocation) ----------------
__device__ float g_gi[(size_t)BT * GG];
__device__ bf16  g_xhi[(size_t)BT * DD];
__device__ bf16  g_xlo[(size_t)BT * DD];
__device__ bf16  g_wih_hi[(size_t)GG * DD];
__device__ bf16  g_wih_lo[(size_t)GG * DD];
__device__ bf16  g_whh_hi[(size_t)GG * HH];
__device__ bf16  g_whh_lo[(size_t)GG * HH];
__device__ float g_h[2][BATCH * HH];
__device__ bf16  g_hhi[2][BATCH * HH];
__device__ bf16  g_hlo[2][BATCH * HH];
__device__ float g_mask[BT];
__device__ unsigned g_bar_arrive;   // zero-init; drains back to 0 (replay-safe)
__device__ unsigned g_bar_gen;      // monotonic; equality-compared

// ---------------- helpers ----------------
__device__ __forceinline__ void cp16(uint32_t dst, const void* src) {
    asm volatile("cp.async.cg.shared.global [%0], [%1], 16;\n" :: "r"(dst), "l"(src));
}
__device__ __forceinline__ void cp_commit() { asm volatile("cp.async.commit_group;\n"); }
template<int N> __device__ __forceinline__ void cp_wait() {
    asm volatile("cp.async.wait_group %0;\n" :: "n"(N));
}
__device__ __forceinline__ void ldm4(uint32_t* r, uint32_t a) {
    asm volatile("ldmatrix.sync.aligned.m8n8.x4.shared.b16 {%0,%1,%2,%3},[%4];\n"
                 : "=r"(r[0]), "=r"(r[1]), "=r"(r[2]), "=r"(r[3]) : "r"(a));
}
__device__ __forceinline__ void mma16816(float* c, const uint32_t* a, const uint32_t* b) {
    asm volatile("mma.sync.aligned.m16n8k16.row.col.f32.bf16.bf16.f32 "
                 "{%0,%1,%2,%3},{%4,%5,%6,%7},{%8,%9},{%0,%1,%2,%3};\n"
                 : "+f"(c[0]), "+f"(c[1]), "+f"(c[2]), "+f"(c[3])
                 : "r"(a[0]), "r"(a[1]), "r"(a[2]), "r"(a[3]), "r"(b[0]), "r"(b[1]));
}
// 128B-row swizzle: chunk c 0..7, XOR row&7 -> conflict-free LDSM + cp.async
__device__ __forceinline__ uint32_t sw128(uint32_t base, int r, int c) {
    return base + ((uint32_t)r << 7) + ((uint32_t)((c ^ (r & 7)) & 7) << 4);
}
__device__ __forceinline__ float sigmoidf_(float x) { return 1.f / (1.f + expf(-x)); }

// GPU-wide barrier (SCAN_BLOCKS resident blocks; one wave guaranteed).
__device__ __forceinline__ void grid_sync_() {
    __threadfence();
    __syncthreads();
    if (threadIdx.x == 0) {
        unsigned gen;
        asm volatile("ld.acquire.gpu.u32 %0, [%1];" : "=r"(gen) : "l"(&g_bar_gen));
        unsigned ticket = atomicAdd(&g_bar_arrive, 1u);
        if (ticket == SCAN_BLOCKS - 1u) {
            g_bar_arrive = 0u;
            __threadfence();
            atomicAdd(&g_bar_gen, 1u);
        } else {
            unsigned cur;
            do {
                asm volatile("ld.acquire.gpu.u32 %0, [%1];" : "=r"(cur) : "l"(&g_bar_gen));
            } while (cur == gen);
        }
    }
    __syncthreads();
}

// ---------------- prep kernels ----------------
__global__ void mask_kernel(const void* __restrict__ isin) {
    __shared__ int is32;
    if (threadIdx.x == 0) {
        const unsigned char* p = (const unsigned char*)isin;
        int ok = 1;
        for (int i = 0; i < 1024; i++)
            if (p[4 * i + 1] | p[4 * i + 2] | p[4 * i + 3]) { ok = 0; break; }
        is32 = ok;
    }
    __syncthreads();
    int start = blockIdx.x * blockDim.x + threadIdx.x;
    int stride = gridDim.x * blockDim.x;
    if (is32) {
        const int* q = (const int*)isin;
        for (int i = start; i < BT; i += stride) g_mask[i] = q[i] ? 0.f : 1.f;
    } else {
        const unsigned char* q = (const unsigned char*)isin;
        for (int i = start; i < BT; i += stride) g_mask[i] = q[i] ? 0.f : 1.f;
    }
}
__global__ void split_x_kernel(const float* __restrict__ x) {
    size_t n = (size_t)BT * DD;
    for (size_t i = blockIdx.x * (size_t)blockDim.x + threadIdx.x; i < n;
         i += (size_t)gridDim.x * blockDim.x) {
        float f = x[i];
        bf16 h = __float2bfloat16(f);
        g_xhi[i] = h;
        g_xlo[i] = __float2bfloat16(f - __bfloat162float(h));
    }
}
__global__ void split_w_kernel(const float* __restrict__ wih, const float* __restrict__ whh) {
    size_t n = (size_t)GG * DD;
    for (size_t i = blockIdx.x * (size_t)blockDim.x + threadIdx.x; i < n;
         i += (size_t)gridDim.x * blockDim.x) {
        float f = wih[i];
        bf16 h = __float2bfloat16(f);
        g_wih_hi[i] = h;
        g_wih_lo[i] = __float2bfloat16(f - __bfloat162float(h));
        float g = whh[i];
        bf16 hh = __float2bfloat16(g);
        g_whh_hi[i] = hh;
        g_whh_lo[i] = __float2bfloat16(g - __bfloat162float(hh));
    }
}
__global__ void init_h_kernel(const float* __restrict__ hx) {
    int n = BATCH * HH;
    for (int i = blockIdx.x * blockDim.x + threadIdx.x; i < n; i += gridDim.x * blockDim.x) {
        float f = hx[i];
        g_h[0][i] = f;
        bf16 h = __float2bfloat16(f);
        g_hhi[0][i] = h;
        g_hlo[0][i] = __float2bfloat16(f - __bfloat162float(h));
    }
}

// ---------------- gi = x @ W_ih^T + b_ih : 128x128 tiles, K64 chunks ----------------
// grid (GG/128=24, BT/128=256), block 256 (8 warps: wm2 x wn4, warp tile 64x32)
// stage: Ahi 0 (128x128B=16K), Alo +16384, Bhi +32768, Blo +49152   (64KB)
__global__ __launch_bounds__(256, 1) void gi_gemm(const float* __restrict__ b_ih) {
    extern __shared__ __align__(128) char smem_dyn[];
    uint32_t sb = (uint32_t)__cvta_generic_to_shared(smem_dyn);
    int tid = threadIdx.x, lane = tid & 31, w = tid >> 5;
    int wm = w & 1, wn = w >> 1;
    int m0 = blockIdx.y * 128, n0 = blockIdx.x * 128;

    float acc[4][4][4];
#pragma unroll
    for (int i = 0; i < 4; i++)
#pragma unroll
        for (int j = 0; j < 4; j++)
#pragma unroll
            for (int e = 0; e < 4; e++) acc[i][j][e] = 0.f;

    auto load_chunk = [&](int kc, int s) {
        uint32_t o = sb + (uint32_t)s * GI_STAGE;
        int k0 = kc * 64;
#pragma unroll
        for (int v = tid; v < 1024; v += 256) {    // 128 rows x 8 chunks
            int r = v >> 3, c = v & 7;
            size_t ga = (size_t)(m0 + r) * DD + k0 + c * 8;
            cp16(sw128(o, r, c), g_xhi + ga);
            cp16(sw128(o + 16384, r, c), g_xlo + ga);
            size_t gb = (size_t)(n0 + r) * DD + k0 + c * 8;
            cp16(sw128(o + 32768, r, c), g_wih_hi + gb);
            cp16(sw128(o + 49152, r, c), g_wih_lo + gb);
        }
        cp_commit();
    };
    auto ldfrag = [&](uint32_t o, int kk, uint32_t (*ah)[4], uint32_t (*al)[4],
                      uint32_t (*bh)[2], uint32_t (*bl)[2]) {
#pragma unroll
        for (int i = 0; i < 4; i++) {
            int r = wm * 64 + i * 16 + (lane & 15);
            int c = kk * 2 + (lane >> 4);
            ldm4(ah[i], sw128(o, r, c));
            ldm4(al[i], sw128(o + 16384, r, c));
        }
#pragma unroll
        for (int sg = 0; sg < 2; sg++) {
            int r = wn * 32 + sg * 16 + ((lane >> 4) & 1) * 8 + (lane & 7);
            int c = kk * 2 + ((lane >> 3) & 1);
            uint32_t t4[4];
            ldm4(t4, sw128(o + 32768, r, c));
            bh[sg * 2][0] = t4[0]; bh[sg * 2][1] = t4[1];
            bh[sg * 2 + 1][0] = t4[2]; bh[sg * 2 + 1][1] = t4[3];
            ldm4(t4, sw128(o + 49152, r, c));
            bl[sg * 2][0] = t4[0]; bl[sg * 2][1] = t4[1];
            bl[sg * 2 + 1][0] = t4[2]; bl[sg * 2 + 1][1] = t4[3];
        }
    };

    load_chunk(0, 0);
    load_chunk(1, 1);
    for (int kt = 0; kt < 16; kt++) {
        if (kt <= 14) cp_wait<1>(); else cp_wait<0>();
        __syncthreads();
        if (kt <= 13) load_chunk(kt + 2, (kt + 2) % 3);  // stage read in compute(kt-1): freed
        uint32_t o = sb + (uint32_t)(kt % 3) * GI_STAGE;

        uint32_t ah[2][4][4], al[2][4][4], bh[2][4][2], bl[2][4][2];
        ldfrag(o, 0, ah[0], al[0], bh[0], bl[0]);
#pragma unroll
        for (int kk = 0; kk < 4; kk++) {
            int cb = kk & 1;
            if (kk < 3) ldfrag(o, kk + 1, ah[cb ^ 1], al[cb ^ 1], bh[cb ^ 1], bl[cb ^ 1]);
#pragma unroll
            for (int i = 0; i < 4; i++)
#pragma unroll
                for (int j = 0; j < 4; j++) {
                    mma16816(acc[i][j], ah[cb][i], bh[cb][j]);
                    mma16816(acc[i][j], ah[cb][i], bl[cb][j]);
                    mma16816(acc[i][j], al[cb][i], bh[cb][j]);
                }
        }
    }

#pragma unroll
    for (int i = 0; i < 4; i++) {
        int row = m0 + wm * 64 + i * 16 + (lane >> 2);
#pragma unroll
        for (int j = 0; j < 4; j++) {
            int col = n0 + wn * 32 + j * 8 + (lane & 3) * 2;
            float b0 = b_ih[col], b1 = b_ih[col + 1];
            g_gi[(size_t)row * GG + col]           = acc[i][j][0] + b0;
            g_gi[(size_t)row * GG + col + 1]       = acc[i][j][1] + b1;
            g_gi[(size_t)(row + 8) * GG + col]     = acc[i][j][2] + b0;
            g_gi[(size_t)(row + 8) * GG + col + 1] = acc[i][j][3] + b1;
        }
    }
}

// ---------------- persistent GRU scan: single-sync ring + reg double-buffer ----------------
// grid (HH/32=32, BATCH/64=4) = 128 blocks, block 256 (wm2 x wn4)
// stage: Ahi 0 (64x128B), Alo +8192, Bhi +16384 (96x128B), Blo +28672  (40KB)
__global__ __launch_bounds__(256, 1) void gru_scan(const float* __restrict__ b_hh,
                                                   float* __restrict__ hseq_out) {
    extern __shared__ __align__(128) char smem_dyn[];
    uint32_t sb = (uint32_t)__cvta_generic_to_shared(smem_dyn);
    int tid = threadIdx.x, lane = tid & 31, w = tid >> 5;
    int wm = w & 1, wn = w >> 1;
    int m0 = blockIdx.y * 64, n0 = blockIdx.x * 32;

    int cbase = n0 + wn * 8 + (lane & 3) * 2;
    float bias_r[2], bias_z[2], bias_n[2];
#pragma unroll
    for (int e = 0; e < 2; e++) {
        bias_r[e] = b_hh[cbase + e];
        bias_z[e] = b_hh[1024 + cbase + e];
        bias_n[e] = b_hh[2048 + cbase + e];
    }

    auto loadB = [&](int kc, int s) {   // W_hh chunk (t-invariant), no commit
        uint32_t o = sb + (uint32_t)s * SC_STAGE;
        int k0 = kc * 64;
#pragma unroll
        for (int v = tid; v < 768; v += 256) {       // 96 rows x 8 chunks
            int r = v >> 3, c = v & 7;
            size_t grow = (size_t)((r >> 5) * 1024 + n0 + (r & 31));
            size_t go = grow * HH + k0 + c * 8;
            cp16(sw128(o + 16384, r, c), g_whh_hi + go);
            cp16(sw128(o + 28672, r, c), g_whh_lo + go);
        }
    };
    auto loadA = [&](const bf16* Ahi, const bf16* Alo, int kc, int s) {  // no commit
        uint32_t o = sb + (uint32_t)s * SC_STAGE;
        int k0 = kc * 64;
#pragma unroll
        for (int v = tid; v < 512; v += 256) {       // 64 rows x 8 chunks
            int r = v >> 3, c = v & 7;
            size_t go = (size_t)(m0 + r) * HH + k0 + c * 8;
            cp16(sw128(o, r, c), Ahi + go);
            cp16(sw128(o + 8192, r, c), Alo + go);
        }
    };
    auto ldfrag = [&](uint32_t o, int kk, uint32_t (*ah)[4], uint32_t (*al)[4],
                      uint32_t (*b4)[4]) {
#pragma unroll
        for (int i = 0; i < 2; i++) {
            int r = wm * 32 + i * 16 + (lane & 15);
            int c = kk * 2 + (lane >> 4);
            ldm4(ah[i], sw128(o, r, c));
            ldm4(al[i], sw128(o + 8192, r, c));
        }
#pragma unroll
        for (int g = 0; g < 3; g++) {
            // lanes 0-15 address B_hi, lanes 16-31 address B_lo:
            // tiles [hi k0, hi k1, lo k0, lo k1] -> frag hi = {t0,t1}, lo = {t2,t3}
            int r = g * 32 + wn * 8 + (lane & 7);
            int c = kk * 2 + ((lane >> 3) & 1);
            uint32_t bbase = o + 16384 + ((lane & 16) ? 12288u : 0u);
            ldm4(b4[g], sw128(bbase, r, c));
        }
    };

    // prologue: B chunks 0,1 for t=0 (uncommitted)
    loadB(0, 0);
    loadB(1, 1);

    for (int t = 0; t < TT; t++) {
        int cur = t & 1, nxt = cur ^ 1;
        const bf16* Ahi = g_hhi[cur];
        const bf16* Alo = g_hlo[cur];

        loadA(Ahi, Alo, 0, 0); cp_commit();   // G0 = {B0,B1,A0}
        loadA(Ahi, Alo, 1, 1); cp_commit();   // G1 = {A1}

        float acc[3][2][4];
#pragma unroll
        for (int g = 0; g < 3; g++)
#pragma unroll
            for (int i = 0; i < 2; i++)
#pragma unroll
                for (int e = 0; e < 4; e++) acc[g][i][e] = 0.f;

        for (int kt = 0; kt < 16; kt++) {
            if (kt <= 14) cp_wait<1>(); else cp_wait<0>();
            __syncthreads();
            if (kt <= 13) {                    // stage (kt+2)%3 was read in compute(kt-1)
                int s = (kt + 2) % 3;
                loadB(kt + 2, s);
                loadA(Ahi, Alo, kt + 2, s);
                cp_commit();
            }
            uint32_t o = sb + (uint32_t)(kt % 3) * SC_STAGE;

            uint32_t ah[2][2][4], al[2][2][4], b4[2][3][4];
            ldfrag(o, 0, ah[0], al[0], b4[0]);
#pragma unroll
            for (int kk = 0; kk < 4; kk++) {
                int cb = kk & 1;
                if (kk < 3) ldfrag(o, kk + 1, ah[cb ^ 1], al[cb ^ 1], b4[cb ^ 1]);
#pragma unroll
                for (int g = 0; g < 3; g++)
#pragma unroll
                    for (int i = 0; i < 2; i++) {
                        mma16816(acc[g][i], ah[cb][i], &b4[cb][g][0]);   // hi*hi
                        mma16816(acc[g][i], ah[cb][i], &b4[cb][g][2]);   // hi*lo
                        mma16816(acc[g][i], al[cb][i], &b4[cb][g][0]);   // lo*hi
                    }
            }
        }
        __syncthreads();   // all reads of stage 0 (chunk 15) complete before B preload

        if (t + 1 < TT) {  // next step's W chunks (t-invariant), uncommitted
            loadB(0, 0);
            loadB(1, 1);
        }

        // fused gate epilogue
#pragma unroll
        for (int i = 0; i < 2; i++) {
            int rbase = m0 + wm * 32 + i * 16 + (lane >> 2);
#pragma unroll
            for (int e = 0; e < 4; e++) {
                int bb = rbase + ((e >> 1) << 3);
                int hc = cbase + (e & 1);
                float m = g_mask[bb * TT + t];
                float ghr = acc[0][i][e] * m + bias_r[e & 1];
                float ghz = acc[1][i][e] * m + bias_z[e & 1];
                float ghn = acc[2][i][e] * m + bias_n[e & 1];
                const float* gi = g_gi + ((size_t)bb * TT + t) * GG + hc;
                float r = sigmoidf_(gi[0] + ghr);
                float z = sigmoidf_(gi[1024] + ghz);
                float n = tanhf(gi[2048] + r * ghn);
                float hp = g_h[cur][bb * HH + hc];
                float hn2 = (1.f - z) * n + z * (m * hp);
                int idx = bb * HH + hc;
                g_h[nxt][idx] = hn2;
                bf16 hhi = __float2bfloat16(hn2);
                g_hhi[nxt][idx] = hhi;
                g_hlo[nxt][idx] = __float2bfloat16(hn2 - __bfloat162float(hhi));
                hseq_out[((size_t)bb * TT + t) * HH + hc] = hn2;
            }
        }

        grid_sync_();
    }
}

// ---------------- LayerNorm + gated residual ----------------
__device__ __forceinline__ float block_sum(float v, float* red) {
#pragma unroll
    for (int o = 16; o; o >>= 1) v += __shfl_xor_sync(0xffffffffu, v, o);
    int w = threadIdx.x >> 5;
    if ((threadIdx.x & 31) == 0) red[w] = v;
    __syncthreads();
    if (threadIdx.x < 32) {
        float r = (threadIdx.x < 8) ? red[threadIdx.x] : 0.f;
#pragma unroll
        for (int o = 4; o; o >>= 1) r += __shfl_xor_sync(0xffffffffu, r, o);
        if (threadIdx.x == 0) red[0] = r;
    }
    __syncthreads();
    float out = red[0];
    __syncthreads();
    return out;
}

__global__ __launch_bounds__(256) void ln_kernel(const float* __restrict__ x,
                                                 const float* __restrict__ ln_g,
                                                 const float* __restrict__ ln_b,
                                                 const float* __restrict__ res_gate,
                                                 const float* __restrict__ hseq,
                                                 float* __restrict__ y) {
    __shared__ float red[8];
    int row = blockIdx.x;
    int tid = threadIdx.x;
    const float* hr = hseq + (size_t)row * HH;
    float v[4];
    float s = 0.f;
#pragma unroll
    for (int j = 0; j < 4; j++) { v[j] = hr[tid + j * 256]; s += v[j]; }
    float mu = block_sum(s, red) * (1.f / HH);
    float s2 = 0.f;
#pragma unroll
    for (int j = 0; j < 4; j++) { float d = v[j] - mu; s2 += d * d; }
    float var = block_sum(s2, red) * (1.f / HH);
    float rstd = rsqrtf(var + 1e-5f);
#pragma unroll
    for (int j = 0; j < 4; j++) {
        int hc = tid + j * 256;
        float gate = 1.f / (1.f + expf(-res_gate[hc]));
        y[(size_t)row * HH + hc] =
            (v[j] - mu) * rstd * ln_g[hc] + ln_b[hc] + x[(size_t)row * HH + hc] * gate;
    }
}

// ---------------- launch ----------------
extern "C" void kernel_launch(void* const* d_in, const int* in_sizes, int n_in,
                              void* d_out, int out_size) {
    const float* x        = (const float*)d_in[0];
    const float* hx       = (const float*)d_in[1];
    const void*  isin     = d_in[2];
    const float* W_ih     = (const float*)d_in[3];
    const float* W_hh     = (const float*)d_in[4];
    const float* b_ih     = (const float*)d_in[5];
    const float* b_hh     = (const float*)d_in[6];
    const float* ln_g     = (const float*)d_in[7];
    const float* ln_b     = (const float*)d_in[8];
    const float* res_gate = (const float*)d_in[9];
    float* out  = (float*)d_out;
    float* Y    = out;
    float* Hseq = out + (size_t)BT * HH;

    cudaFuncSetAttribute(gi_gemm, cudaFuncAttributeMaxDynamicSharedMemorySize, GI_SMEM);
    cudaFuncSetAttribute(gru_scan, cudaFuncAttributeMaxDynamicSharedMemorySize, SC_SMEM);

    // order chosen so gi_gemm is the 4th launch (ncu sampled slot)
    mask_kernel<<<32, 256>>>(isin);
    split_x_kernel<<<2048, 256>>>(x);
    split_w_kernel<<<1024, 256>>>(W_ih, W_hh);

    dim3 g1(GG / 128, BT / 128);
    gi_gemm<<<g1, 256, GI_SMEM>>>(b_ih);

    init_h_kernel<<<256, 256>>>(hx);

    dim3 g2(HH / 32, BATCH / 64);   // 32 x 4 = 128 persistent blocks
    gru_scan<<<g2, 256, SC_SMEM>>>(b_hh, Hseq);

    ln_kernel<<<BT, 256>>>(x, ln_g, ln_b, res_gate, Hseq, Y);
}

// round 12
// speedup vs baseline: 1.5440x; 1.1775x over previous
#include <cuda_runtime.h>
#include <cuda_bf16.h>
#include <cstdint>
#include <cstddef>

typedef __nv_bfloat16 bf16;

#define BATCH 256
#define TT    128
#define DD    1024
#define HH    1024
#define GG    3072
#define BT    (BATCH*TT)
#define GROUP_BLOCKS 32   // blocks per m-group barrier

#define GI_STAGE 65536
#define GI_NS    3
#define GI_SMEM  (GI_NS*GI_STAGE)          // 196608
#define SC_STAGE 40960
#define SC_NS    3
#define SGI_BYTES (64*400)                  // padded gi slice (64 rows x 400B)
#define SC_SMEM  (SC_NS*SC_STAGE + SGI_BYTES)  // 148480

// ---------------- device scratch (static; no runtime allocation) ----------------
__device__ float g_gi[(size_t)BT * GG];
__device__ bf16  g_xhi[(size_t)BT * DD];
__device__ bf16  g_xlo[(size_t)BT * DD];
__device__ bf16  g_wih_hi[(size_t)GG * DD];
__device__ bf16  g_wih_lo[(size_t)GG * DD];
__device__ bf16  g_whh_hi[(size_t)GG * HH];
__device__ bf16  g_whh_lo[(size_t)GG * HH];
__device__ float g_h[2][BATCH * HH];
__device__ bf16  g_hhi[2][BATCH * HH];
__device__ bf16  g_hlo[2][BATCH * HH];
__device__ float g_mask[BT];
__device__ unsigned g_bar_arr[4];   // zero-init; drains back to 0 (replay-safe)
__device__ unsigned g_bar_gen4[4];  // monotonic; equality-compared

// ---------------- helpers ----------------
__device__ __forceinline__ void cp16(uint32_t dst, const void* src) {
    asm volatile("cp.async.cg.shared.global [%0], [%1], 16;\n" :: "r"(dst), "l"(src));
}
__device__ __forceinline__ void cp_commit() { asm volatile("cp.async.commit_group;\n"); }
template<int N> __device__ __forceinline__ void cp_wait() {
    asm volatile("cp.async.wait_group %0;\n" :: "n"(N));
}
__device__ __forceinline__ void ldm4(uint32_t* r, uint32_t a) {
    asm volatile("ldmatrix.sync.aligned.m8n8.x4.shared.b16 {%0,%1,%2,%3},[%4];\n"
                 : "=r"(r[0]), "=r"(r[1]), "=r"(r[2]), "=r"(r[3]) : "r"(a));
}
__device__ __forceinline__ void mma16816(float* c, const uint32_t* a, const uint32_t* b) {
    asm volatile("mma.sync.aligned.m16n8k16.row.col.f32.bf16.bf16.f32 "
                 "{%0,%1,%2,%3},{%4,%5,%6,%7},{%8,%9},{%0,%1,%2,%3};\n"
                 : "+f"(c[0]), "+f"(c[1]), "+f"(c[2]), "+f"(c[3])
                 : "r"(a[0]), "r"(a[1]), "r"(a[2]), "r"(a[3]), "r"(b[0]), "r"(b[1]));
}
// 128B-row swizzle: chunk c 0..7, XOR row&7 -> conflict-free LDSM + cp.async
__device__ __forceinline__ uint32_t sw128(uint32_t base, int r, int c) {
    return base + ((uint32_t)r << 7) + ((uint32_t)((c ^ (r & 7)) & 7) << 4);
}
__device__ __forceinline__ float sigmoidf_(float x) { return 1.f / (1.f + expf(-x)); }

// group barrier: 32 blocks sharing one m0 (batch-row slice)
__device__ __forceinline__ void group_sync_(int gidx) {
    __threadfence();
    __syncthreads();
    if (threadIdx.x == 0) {
        unsigned gen;
        asm volatile("ld.acquire.gpu.u32 %0, [%1];" : "=r"(gen) : "l"(&g_bar_gen4[gidx]));
        unsigned ticket = atomicAdd(&g_bar_arr[gidx], 1u);
        if (ticket == GROUP_BLOCKS - 1u) {
            g_bar_arr[gidx] = 0u;
            __threadfence();
            atomicAdd(&g_bar_gen4[gidx], 1u);
        } else {
            unsigned cur;
            do {
                asm volatile("ld.acquire.gpu.u32 %0, [%1];" : "=r"(cur) : "l"(&g_bar_gen4[gidx]));
            } while (cur == gen);
        }
    }
    __syncthreads();
}

// ---------------- prep kernels ----------------
__global__ void split_x_kernel(const float* __restrict__ x) {
    size_t n = (size_t)BT * DD;
    for (size_t i = blockIdx.x * (size_t)blockDim.x + threadIdx.x; i < n;
         i += (size_t)gridDim.x * blockDim.x) {
        float f = x[i];
        bf16 h = __float2bfloat16(f);
        g_xhi[i] = h;
        g_xlo[i] = __float2bfloat16(f - __bfloat162float(h));
    }
}
__global__ void split_w_kernel(const float* __restrict__ wih, const float* __restrict__ whh) {
    size_t n = (size_t)GG * DD;
    for (size_t i = blockIdx.x * (size_t)blockDim.x + threadIdx.x; i < n;
         i += (size_t)gridDim.x * blockDim.x) {
        float f = wih[i];
        bf16 h = __float2bfloat16(f);
        g_wih_hi[i] = h;
        g_wih_lo[i] = __float2bfloat16(f - __bfloat162float(h));
        float g = whh[i];
        bf16 hh = __float2bfloat16(g);
        g_whh_hi[i] = hh;
        g_whh_lo[i] = __float2bfloat16(g - __bfloat162float(hh));
    }
}

// ---------------- gi = x @ W_ih^T + b_ih : 128x128 tiles, K64 chunks ----------------
// grid (GG/128=24, BT/128=256), block 256 (8 warps: wm2 x wn4, warp tile 64x32)
__global__ __launch_bounds__(256, 1) void gi_gemm(const float* __restrict__ b_ih) {
    extern __shared__ __align__(128) char smem_dyn[];
    uint32_t sb = (uint32_t)__cvta_generic_to_shared(smem_dyn);
    int tid = threadIdx.x, lane = tid & 31, w = tid >> 5;
    int wm = w & 1, wn = w >> 1;
    int m0 = blockIdx.y * 128, n0 = blockIdx.x * 128;

    float acc[4][4][4];
#pragma unroll
    for (int i = 0; i < 4; i++)
#pragma unroll
        for (int j = 0; j < 4; j++)
#pragma unroll
            for (int e = 0; e < 4; e++) acc[i][j][e] = 0.f;

    auto load_chunk = [&](int kc, int s) {
        uint32_t o = sb + (uint32_t)s * GI_STAGE;
        int k0 = kc * 64;
#pragma unroll
        for (int v = tid; v < 1024; v += 256) {    // 128 rows x 8 chunks
            int r = v >> 3, c = v & 7;
            size_t ga = (size_t)(m0 + r) * DD + k0 + c * 8;
            cp16(sw128(o, r, c), g_xhi + ga);
            cp16(sw128(o + 16384, r, c), g_xlo + ga);
            size_t gb = (size_t)(n0 + r) * DD + k0 + c * 8;
            cp16(sw128(o + 32768, r, c), g_wih_hi + gb);
            cp16(sw128(o + 49152, r, c), g_wih_lo + gb);
        }
        cp_commit();
    };
    auto ldfrag = [&](uint32_t o, int kk, uint32_t (*ah)[4], uint32_t (*al)[4],
                      uint32_t (*bh)[2], uint32_t (*bl)[2]) {
#pragma unroll
        for (int i = 0; i < 4; i++) {
            int r = wm * 64 + i * 16 + (lane & 15);
            int c = kk * 2 + (lane >> 4);
            ldm4(ah[i], sw128(o, r, c));
            ldm4(al[i], sw128(o + 16384, r, c));
        }
#pragma unroll
        for (int sg = 0; sg < 2; sg++) {
            int r = wn * 32 + sg * 16 + ((lane >> 4) & 1) * 8 + (lane & 7);
            int c = kk * 2 + ((lane >> 3) & 1);
            uint32_t t4[4];
            ldm4(t4, sw128(o + 32768, r, c));
            bh[sg * 2][0] = t4[0]; bh[sg * 2][1] = t4[1];
            bh[sg * 2 + 1][0] = t4[2]; bh[sg * 2 + 1][1] = t4[3];
            ldm4(t4, sw128(o + 49152, r, c));
            bl[sg * 2][0] = t4[0]; bl[sg * 2][1] = t4[1];
            bl[sg * 2 + 1][0] = t4[2]; bl[sg * 2 + 1][1] = t4[3];
        }
    };

    load_chunk(0, 0);
    load_chunk(1, 1);
    for (int kt = 0; kt < 16; kt++) {
        if (kt <= 14) cp_wait<1>(); else cp_wait<0>();
        __syncthreads();
        if (kt <= 13) load_chunk(kt + 2, (kt + 2) % 3);
        uint32_t o = sb + (uint32_t)(kt % 3) * GI_STAGE;

        uint32_t ah[2][4][4], al[2][4][4], bh[2][4][2], bl[2][4][2];
        ldfrag(o, 0, ah[0], al[0], bh[0], bl[0]);
#pragma unroll
        for (int kk = 0; kk < 4; kk++) {
            int cb = kk & 1;
            if (kk < 3) ldfrag(o, kk + 1, ah[cb ^ 1], al[cb ^ 1], bh[cb ^ 1], bl[cb ^ 1]);
#pragma unroll
            for (int i = 0; i < 4; i++)
#pragma unroll
                for (int j = 0; j < 4; j++) {
                    mma16816(acc[i][j], ah[cb][i], bh[cb][j]);
                    mma16816(acc[i][j], ah[cb][i], bl[cb][j]);
                    mma16816(acc[i][j], al[cb][i], bh[cb][j]);
                }
        }
    }

#pragma unroll
    for (int i = 0; i < 4; i++) {
        int row = m0 + wm * 64 + i * 16 + (lane >> 2);
#pragma unroll
        for (int j = 0; j < 4; j++) {
            int col = n0 + wn * 32 + j * 8 + (lane & 3) * 2;
            float b0 = b_ih[col], b1 = b_ih[col + 1];
            g_gi[(size_t)row * GG + col]           = acc[i][j][0] + b0;
            g_gi[(size_t)row * GG + col + 1]       = acc[i][j][1] + b1;
            g_gi[(size_t)(row + 8) * GG + col]     = acc[i][j][2] + b0;
            g_gi[(size_t)(row + 8) * GG + col + 1] = acc[i][j][3] + b1;
        }
    }
}

// ---------------- persistent GRU scan: group barriers + gi smem prefetch ----------------
// grid (HH/32=32, BATCH/64=4) = 128 blocks, block 256 (wm2 x wn4)
// stage: Ahi 0 (64x128B), Alo +8192, Bhi +16384 (96x128B), Blo +28672  (40KB)
// gi slice: +3*SC_STAGE, 64 rows x 400B (3 gates x 32 floats, 16B padded rows)
__global__ __launch_bounds__(256, 1) void gru_scan(const float* __restrict__ b_hh,
                                                   float* __restrict__ hseq_out,
                                                   const void* __restrict__ isin,
                                                   const float* __restrict__ hx) {
    extern __shared__ __align__(128) char smem_dyn[];
    uint32_t sb = (uint32_t)__cvta_generic_to_shared(smem_dyn);
    uint32_t sgi = sb + 3u * SC_STAGE;
    int tid = threadIdx.x, lane = tid & 31, w = tid >> 5;
    int wm = w & 1, wn = w >> 1;
    int m0 = blockIdx.y * 64, n0 = blockIdx.x * 32;
    int gidx = blockIdx.y;

    // ---- folded init (group-partitioned): dtype probe, mask, h init ----
    {
        const unsigned char* p = (const unsigned char*)isin;
        int bad = 0;
#pragma unroll
        for (int j = 0; j < 4; j++) {
            int i = tid * 4 + j;   // first 1024 int32 slots
            bad |= p[4 * i + 1] | p[4 * i + 2] | p[4 * i + 3];
        }
        int is32 = !__syncthreads_or(bad);
        int r0 = m0 + (int)blockIdx.x * 2;          // this block's 2 batch rows
        for (int v = tid; v < 2 * HH; v += 256) {
            int r = r0 + (v >> 10), cidx = v & 1023;
            float f = hx[r * HH + cidx];
            g_h[0][r * HH + cidx] = f;
            bf16 h = __float2bfloat16(f);
            g_hhi[0][r * HH + cidx] = h;
            g_hlo[0][r * HH + cidx] = __float2bfloat16(f - __bfloat162float(h));
        }
        if (is32) {
            const int* q = (const int*)isin;
            for (int v = tid; v < 2 * TT; v += 256) {
                int i = r0 * TT + v;
                g_mask[i] = q[i] ? 0.f : 1.f;
            }
        } else {
            for (int v = tid; v < 2 * TT; v += 256) {
                int i = r0 * TT + v;
                g_mask[i] = p[i] ? 0.f : 1.f;
            }
        }
    }
    group_sync_(gidx);

    int cbase = n0 + wn * 8 + (lane & 3) * 2;
    float bias_r[2], bias_z[2], bias_n[2];
#pragma unroll
    for (int e = 0; e < 2; e++) {
        bias_r[e] = b_hh[cbase + e];
        bias_z[e] = b_hh[1024 + cbase + e];
        bias_n[e] = b_hh[2048 + cbase + e];
    }

    auto loadB = [&](int kc, int s) {   // W_hh chunk (t-invariant), no commit
        uint32_t o = sb + (uint32_t)s * SC_STAGE;
        int k0 = kc * 64;
#pragma unroll
        for (int v = tid; v < 768; v += 256) {       // 96 rows x 8 chunks
            int r = v >> 3, c = v & 7;
            size_t grow = (size_t)((r >> 5) * 1024 + n0 + (r & 31));
            size_t go = grow * HH + k0 + c * 8;
            cp16(sw128(o + 16384, r, c), g_whh_hi + go);
            cp16(sw128(o + 28672, r, c), g_whh_lo + go);
        }
    };
    auto loadA = [&](const bf16* Ahi, const bf16* Alo, int kc, int s) {  // no commit
        uint32_t o = sb + (uint32_t)s * SC_STAGE;
        int k0 = kc * 64;
#pragma unroll
        for (int v = tid; v < 512; v += 256) {       // 64 rows x 8 chunks
            int r = v >> 3, c = v & 7;
            size_t go = (size_t)(m0 + r) * HH + k0 + c * 8;
            cp16(sw128(o, r, c), Ahi + go);
            cp16(sw128(o + 8192, r, c), Alo + go);
        }
    };
    auto ldfrag = [&](uint32_t o, int kk, uint32_t (*ah)[4], uint32_t (*al)[4],
                      uint32_t (*b4)[4]) {
#pragma unroll
        for (int i = 0; i < 2; i++) {
            int r = wm * 32 + i * 16 + (lane & 15);
            int c = kk * 2 + (lane >> 4);
            ldm4(ah[i], sw128(o, r, c));
            ldm4(al[i], sw128(o + 8192, r, c));
        }
#pragma unroll
        for (int g = 0; g < 3; g++) {
            int r = g * 32 + wn * 8 + (lane & 7);
            int c = kk * 2 + ((lane >> 3) & 1);
            uint32_t bbase = o + 16384 + ((lane & 16) ? 12288u : 0u);
            ldm4(b4[g], sw128(bbase, r, c));
        }
    };

    // prologue: B chunks 0,1 for t=0 (uncommitted)
    loadB(0, 0);
    loadB(1, 1);

    for (int t = 0; t < TT; t++) {
        int cur = t & 1, nxt = cur ^ 1;
        const bf16* Ahi = g_hhi[cur];
        const bf16* Alo = g_hlo[cur];

        // prefetch gi[:, t] slice into smem (h-independent; rides in group G0)
        for (int v = tid; v < 1536; v += 256) {
            int r = v / 24, rem = v % 24, g = rem >> 3, c4 = rem & 7;
            const float* src = g_gi + ((size_t)(m0 + r) * TT + t) * GG + g * 1024 + n0 + c4 * 4;
            cp16(sgi + r * 400 + g * 128 + c4 * 16, src);
        }

        loadA(Ahi, Alo, 0, 0); cp_commit();   // G0 = {B0,B1,gi,A0}
        loadA(Ahi, Alo, 1, 1); cp_commit();   // G1 = {A1}

        float acc[3][2][4];
#pragma unroll
        for (int g = 0; g < 3; g++)
#pragma unroll
            for (int i = 0; i < 2; i++)
#pragma unroll
                for (int e = 0; e < 4; e++) acc[g][i][e] = 0.f;

        for (int kt = 0; kt < 16; kt++) {
            if (kt <= 14) cp_wait<1>(); else cp_wait<0>();
            __syncthreads();
            if (kt <= 13) {                    // stage (kt+2)%3 was read in compute(kt-1)
                int s = (kt + 2) % 3;
                loadB(kt + 2, s);
                loadA(Ahi, Alo, kt + 2, s);
                cp_commit();
            }
            uint32_t o = sb + (uint32_t)(kt % 3) * SC_STAGE;

            uint32_t ah[2][2][4], al[2][2][4], b4[2][3][4];
            ldfrag(o, 0, ah[0], al[0], b4[0]);
#pragma unroll
            for (int kk = 0; kk < 4; kk++) {
                int cb = kk & 1;
                if (kk < 3) ldfrag(o, kk + 1, ah[cb ^ 1], al[cb ^ 1], b4[cb ^ 1]);
#pragma unroll
                for (int g = 0; g < 3; g++)
#pragma unroll
                    for (int i = 0; i < 2; i++) {
                        mma16816(acc[g][i], ah[cb][i], &b4[cb][g][0]);   // hi*hi
                        mma16816(acc[g][i], ah[cb][i], &b4[cb][g][2]);   // hi*lo
                        mma16816(acc[g][i], al[cb][i], &b4[cb][g][0]);   // lo*hi
                    }
            }
        }
        __syncthreads();   // reads of stage 0 (chunk 15) complete before B preload

        if (t + 1 < TT) {  // next step's W chunks (t-invariant), uncommitted
            loadB(0, 0);
            loadB(1, 1);
        }

        // fused gate epilogue (gi from smem)
#pragma unroll
        for (int i = 0; i < 2; i++) {
            int rbase = m0 + wm * 32 + i * 16 + (lane >> 2);
#pragma unroll
            for (int e = 0; e < 4; e++) {
                int bb = rbase + ((e >> 1) << 3);
                int hc = cbase + (e & 1);
                int rloc = bb - m0;
                int hcl = wn * 8 + (lane & 3) * 2 + (e & 1);
                const float* gg = (const float*)(smem_dyn + 3 * SC_STAGE + rloc * 400);
                float m = g_mask[bb * TT + t];
                float ghr = acc[0][i][e] * m + bias_r[e & 1];
                float ghz = acc[1][i][e] * m + bias_z[e & 1];
                float ghn = acc[2][i][e] * m + bias_n[e & 1];
                float r = sigmoidf_(gg[hcl] + ghr);
                float z = sigmoidf_(gg[32 + hcl] + ghz);
                float n = tanhf(gg[64 + hcl] + r * ghn);
                float hp = g_h[cur][bb * HH + hc];
                float hn2 = (1.f - z) * n + z * (m * hp);
                int idx = bb * HH + hc;
                g_h[nxt][idx] = hn2;
                bf16 hhi = __float2bfloat16(hn2);
                g_hhi[nxt][idx] = hhi;
                g_hlo[nxt][idx] = __float2bfloat16(hn2 - __bfloat162float(hhi));
                hseq_out[((size_t)bb * TT + t) * HH + hc] = hn2;
            }
        }

        group_sync_(gidx);
    }
}

// ---------------- LayerNorm + gated residual ----------------
__device__ __forceinline__ float block_sum(float v, float* red) {
#pragma unroll
    for (int o = 16; o; o >>= 1) v += __shfl_xor_sync(0xffffffffu, v, o);
    int w = threadIdx.x >> 5;
    if ((threadIdx.x & 31) == 0) red[w] = v;
    __syncthreads();
    if (threadIdx.x < 32) {
        float r = (threadIdx.x < 8) ? red[threadIdx.x] : 0.f;
#pragma unroll
        for (int o = 4; o; o >>= 1) r += __shfl_xor_sync(0xffffffffu, r, o);
        if (threadIdx.x == 0) red[0] = r;
    }
    __syncthreads();
    float out = red[0];
    __syncthreads();
    return out;
}

__global__ __launch_bounds__(256) void ln_kernel(const float* __restrict__ x,
                                                 const float* __restrict__ ln_g,
                                                 const float* __restrict__ ln_b,
                                                 const float* __restrict__ res_gate,
                                                 const float* __restrict__ hseq,
                                                 float* __restrict__ y) {
    __shared__ float red[8];
    int row = blockIdx.x;
    int tid = threadIdx.x;
    const float* hr = hseq + (size_t)row * HH;
    float v[4];
    float s = 0.f;
#pragma unroll
    for (int j = 0; j < 4; j++) { v[j] = hr[tid + j * 256]; s += v[j]; }
    float mu = block_sum(s, red) * (1.f / HH);
    float s2 = 0.f;
#pragma unroll
    for (int j = 0; j < 4; j++) { float d = v[j] - mu; s2 += d * d; }
    float var = block_sum(s2, red) * (1.f / HH);
    float rstd = rsqrtf(var + 1e-5f);
#pragma unroll
    for (int j = 0; j < 4; j++) {
        int hc = tid + j * 256;
        float gate = 1.f / (1.f + expf(-res_gate[hc]));
        y[(size_t)row * HH + hc] =
            (v[j] - mu) * rstd * ln_g[hc] + ln_b[hc] + x[(size_t)row * HH + hc] * gate;
    }
}

// ---------------- launch ----------------
extern "C" void kernel_launch(void* const* d_in, const int* in_sizes, int n_in,
                              void* d_out, int out_size) {
    const float* x        = (const float*)d_in[0];
    const float* hx       = (const float*)d_in[1];
    const void*  isin     = d_in[2];
    const float* W_ih     = (const float*)d_in[3];
    const float* W_hh     = (const float*)d_in[4];
    const float* b_ih     = (const float*)d_in[5];
    const float* b_hh     = (const float*)d_in[6];
    const float* ln_g     = (const float*)d_in[7];
    const float* ln_b     = (const float*)d_in[8];
    const float* res_gate = (const float*)d_in[9];
    float* out  = (float*)d_out;
    float* Y    = out;
    float* Hseq = out + (size_t)BT * HH;

    cudaFuncSetAttribute(gi_gemm, cudaFuncAttributeMaxDynamicSharedMemorySize, GI_SMEM);
    cudaFuncSetAttribute(gru_scan, cudaFuncAttributeMaxDynamicSharedMemorySize, SC_SMEM);

    // order: scan is the 4th launch (ncu sampled slot)
    split_x_kernel<<<2048, 256>>>(x);
    split_w_kernel<<<1024, 256>>>(W_ih, W_hh);

    dim3 g1(GG / 128, BT / 128);
    gi_gemm<<<g1, 256, GI_SMEM>>>(b_ih);

    dim3 g2(HH / 32, BATCH / 64);   // 32 x 4 = 128 persistent blocks
    gru_scan<<<g2, 256, SC_SMEM>>>(b_hh, Hseq, isin, hx);

    ln_kernel<<<BT, 256>>>(x, ln_g, ln_b, res_gate, Hseq, Y);
}